// round 5
// baseline (speedup 1.0000x reference)
#include <cuda_runtime.h>
#include <cstdint>

#define BB 2048
#define TT 256
#define NVV 32
#define HH 64
#define GG 192
#define LL 32
#define OHH 64

__device__ float g_h[BB * HH];
__device__ float g_z0[BB * LL];
__device__ float g_zf[BB * LL];
__device__ float g_klrow[BB];
// xp[t][g][b] : t = scan step (time-reversed), 402 MB scratch
__device__ float g_xp[(size_t)TT * GG * BB];

__device__ __forceinline__ float sigf(float x) {
    return __fdividef(1.f, 1.f + __expf(-x));
}
__device__ __forceinline__ float tanhf_fast(float x) {
    return 1.f - __fdividef(2.f, __expf(2.f * x) + 1.f);
}

// packed fp32x2 helpers (Blackwell FFMA2)
__device__ __forceinline__ void ffma2(unsigned long long &d,
                                      unsigned long long a,
                                      unsigned long long b) {
    asm("fma.rn.f32x2 %0, %1, %2, %0;" : "+l"(d) : "l"(a), "l"(b));
}
__device__ __forceinline__ unsigned long long dup2(float v) {
    unsigned long long r;
    asm("mov.b64 %0, {%1, %1};" : "=l"(r) : "f"(v));
    return r;
}
__device__ __forceinline__ unsigned long long pack2(float a, float b) {
    unsigned long long r;
    asm("mov.b64 %0, {%1, %2};" : "=l"(r) : "f"(a), "f"(b));
    return r;
}
__device__ __forceinline__ float2 upk(unsigned long long v) {
    float2 t;
    asm("mov.b64 {%0, %1}, %2;" : "=f"(t.x), "=f"(t.y) : "l"(v));
    return t;
}

// =====================================================================
// xp GEMM: xp[t][g][b] = b_ih[g] + sum_f W_ih[g][f] * x[b][255-t][f]
// grid (16 b-blocks, 256 t), 256 threads. Thread tile: 12 g x 8 b.
// SMEM: dup weights [(f*192+g)*2] 98KB | xT [f][132] 33KB
// =====================================================================
#define XP_SMEM_B ((24576 + 64 * 132) * 4)

__global__ void __launch_bounds__(256, 1) xp_kernel(
    const float* __restrict__ values, const float* __restrict__ maskp,
    const float* __restrict__ W_ih, const float* __restrict__ b_ih)
{
    extern __shared__ float sm[];
    float* sW = sm;               // [(f*192+g)*2]
    float* sX = sW + 24576;       // [f][132]

    const int tid = threadIdx.x;
    const int bblk = blockIdx.x;       // 0..15
    const int t = blockIdx.y;          // scan step
    const int tt = TT - 1 - t;         // original time index
    const int bbase = bblk * 128;

    for (int i = tid; i < GG * HH; i += 256) {
        int g = i >> 6, f = i & 63;
        float w = W_ih[i];
        *(float2*)(sW + (f * GG + g) * 2) = make_float2(w, w);
    }
    for (int i = tid; i < 128 * HH; i += 256) {
        int bl = i >> 6, f = i & 63;
        size_t base = (size_t)(bbase + bl) * TT * NVV + (size_t)tt * NVV;
        sX[f * 132 + bl] = (f < NVV) ? values[base + f] : maskp[base + f - NVV];
    }
    __syncthreads();

    const int g0 = (tid & 15) * 12;
    const int b0 = (tid >> 4) * 8;

    unsigned long long a[12][4];
    #pragma unroll
    for (int i = 0; i < 12; i++) {
        unsigned long long bi = dup2(__ldg(b_ih + g0 + i));
        #pragma unroll
        for (int q = 0; q < 4; q++) a[i][q] = bi;
    }

    #pragma unroll 4
    for (int f = 0; f < HH; f++) {
        const float* wb = sW + (f * GG + g0) * 2;
        unsigned long long wv[12];
        #pragma unroll
        for (int p = 0; p < 6; p++) {
            ulonglong2 w2 = *(const ulonglong2*)(wb + p * 4);
            wv[p * 2] = w2.x; wv[p * 2 + 1] = w2.y;
        }
        ulonglong2 xA = *(const ulonglong2*)(sX + f * 132 + b0);
        ulonglong2 xB = *(const ulonglong2*)(sX + f * 132 + b0 + 4);
        unsigned long long xd[4] = {xA.x, xA.y, xB.x, xB.y};
        #pragma unroll
        for (int i = 0; i < 12; i++)
            #pragma unroll
            for (int q = 0; q < 4; q++)
                ffma2(a[i][q], wv[i], xd[q]);
    }

    #pragma unroll
    for (int i = 0; i < 12; i++) {
        size_t dst = ((size_t)t * GG + g0 + i) * BB + bbase + b0;
        float2 p0 = upk(a[i][0]), p1 = upk(a[i][1]);
        float2 p2 = upk(a[i][2]), p3 = upk(a[i][3]);
        *(float4*)(g_xp + dst)     = make_float4(p0.x, p0.y, p1.x, p1.y);
        *(float4*)(g_xp + dst + 4) = make_float4(p2.x, p2.y, p3.x, p3.y);
    }
}

// =====================================================================
// GRU scan: 128 CTAs x 256 thr, 16 rows/CTA. Only W_hh matvec inside.
// Thread: 1 j (0..63) x 3 gates x 4 rows. Weights packed [f][j][12]:
//   {R pair, Z pair, N pair} dup'd, stride 12 floats (48B, conflict-free).
// h kept in SMEM [j][20] for matvec; h_old + seq mask in registers.
// =====================================================================
#define GRU_SMEM_F (64 * 64 * 12 + 1280)
#define GRU_SMEM_B (GRU_SMEM_F * 4 + 64)

__global__ void __launch_bounds__(256, 1) gru_kernel(
    const int* __restrict__ seqlen,
    const float* __restrict__ W_hh, const float* __restrict__ b_hh)
{
    extern __shared__ float sm[];
    float* sW = sm;                 // [f][j][12]
    float* sh = sW + 64 * 64 * 12;  // [j][20]

    const int tid  = threadIdx.x;
    const int row0 = blockIdx.x * 16;

    for (int i = tid; i < GG * HH; i += 256) {
        int g = i >> 6, f = i & 63;
        int j = g & 63, gate = g >> 6;
        float w = W_hh[i];
        float* d = sW + ((f * 64 + j) * 12) + gate * 2;
        d[0] = w; d[1] = w;
    }
    for (int i = tid; i < 1280; i += 256) sh[i] = 0.f;

    const int j  = tid >> 2;       // 0..63
    const int rg = tid & 3;        // 0..3
    const int r0 = rg * 4;

    const float bhr = __ldg(b_hh + j);
    const float bhz = __ldg(b_hh + 64 + j);
    const unsigned long long bhn2 = dup2(__ldg(b_hh + 128 + j));

    int seqr[4];
    #pragma unroll
    for (int c = 0; c < 4; c++) seqr[c] = __ldg(seqlen + row0 + r0 + c);

    float hprev[4] = {0.f, 0.f, 0.f, 0.f};

    // current xp registers (step 0)
    size_t xbase = (size_t)j * BB + row0 + r0;
    float4 xR = *(const float4*)(g_xp + xbase);
    float4 xZ = *(const float4*)(g_xp + xbase + (size_t)64 * BB);
    float4 xN = *(const float4*)(g_xp + xbase + (size_t)128 * BB);
    __syncthreads();

    for (int t = 0; t < TT; t++) {
        float4 pR, pZ, pN;
        if (t + 1 < TT) {
            size_t nb = ((size_t)(t + 1) * GG + j) * BB + row0 + r0;
            pR = *(const float4*)(g_xp + nb);
            pZ = *(const float4*)(g_xp + nb + (size_t)64 * BB);
            pN = *(const float4*)(g_xp + nb + (size_t)128 * BB);
        }

        unsigned long long ar0 = pack2(xR.x + bhr, xR.y + bhr);
        unsigned long long ar1 = pack2(xR.z + bhr, xR.w + bhr);
        unsigned long long az0 = pack2(xZ.x + bhz, xZ.y + bhz);
        unsigned long long az1 = pack2(xZ.z + bhz, xZ.w + bhz);
        unsigned long long an0 = bhn2, an1 = bhn2;

        const float* wj = sW + j * 12;
        #pragma unroll 8
        for (int f = 0; f < HH; f++) {
            const float* wp = wj + f * 768;
            ulonglong2 wRZ = *(const ulonglong2*)wp;
            unsigned long long wN = *(const unsigned long long*)(wp + 4);
            ulonglong2 hv = *(const ulonglong2*)(sh + f * 20 + r0);
            ffma2(ar0, wRZ.x, hv.x);
            ffma2(az0, wRZ.y, hv.x);
            ffma2(an0, wN,    hv.x);
            ffma2(ar1, wRZ.x, hv.y);
            ffma2(az1, wRZ.y, hv.y);
            ffma2(an1, wN,    hv.y);
        }

        float2 vr0 = upk(ar0), vr1 = upk(ar1);
        float2 vz0 = upk(az0), vz1 = upk(az1);
        float2 vn0 = upk(an0), vn1 = upk(an1);
        float fr[4] = {vr0.x, vr0.y, vr1.x, vr1.y};
        float fz[4] = {vz0.x, vz0.y, vz1.x, vz1.y};
        float fh[4] = {vn0.x, vn0.y, vn1.x, vn1.y};
        float fx[4] = {xN.x, xN.y, xN.z, xN.w};
        float hnew[4];
        #pragma unroll
        for (int c = 0; c < 4; c++) {
            float rr = sigf(fr[c]);
            float zz = sigf(fz[c]);
            float nn = tanhf_fast(fx[c] + rr * fh[c]);
            float hn = (1.f - zz) * nn + zz * hprev[c];
            hnew[c] = (t < seqr[c]) ? hn : hprev[c];
            hprev[c] = hnew[c];
        }
        __syncthreads();
        *(float4*)(sh + j * 20 + r0) = make_float4(hnew[0], hnew[1], hnew[2], hnew[3]);
        xR = pR; xZ = pZ; xN = pN;
        __syncthreads();
    }

    #pragma unroll
    for (int c = 0; c < 4; c++)
        g_h[(size_t)(row0 + r0 + c) * HH + j] = hprev[c];
}

// =====================================================================
// z0: one warp per row (8 warps/CTA, 256 CTAs)
// =====================================================================
__global__ void __launch_bounds__(256) z0_kernel(
    const float* __restrict__ Wz0, const float* __restrict__ bz0,
    const float* __restrict__ eps)
{
    __shared__ float sH[8][64];
    const int w = threadIdx.x >> 5, l = threadIdx.x & 31;
    const int row = blockIdx.x * 8 + w;
    sH[w][l]      = g_h[(size_t)row * HH + l];
    sH[w][l + 32] = g_h[(size_t)row * HH + l + 32];
    __syncwarp();
    float m = bz0[l], lv = bz0[l + 32];
    #pragma unroll 8
    for (int f = 0; f < HH; f++) {
        float hf = sH[w][f];
        m  = fmaf(__ldg(Wz0 + l * HH + f), hf, m);
        lv = fmaf(__ldg(Wz0 + (l + 32) * HH + f), hf, lv);
    }
    g_z0[(size_t)row * LL + l] = m + eps[(size_t)row * LL + l] * __expf(0.5f * lv);
    float kterm = 1.f + lv - m * m - __expf(lv);
    #pragma unroll
    for (int off = 16; off; off >>= 1) kterm += __shfl_down_sync(0xffffffffu, kterm, off);
    if (l == 0) g_klrow[row] = kterm;
}

// =====================================================================
// ODE: fixed-step RK4, NSTEP steps over [0,48]. 128 CTAs x 128 thr, 16 rows.
// =====================================================================
#define NSTEP 8
#define ODE_SMEM_F (2048 + 4096 + 2048 + 64 + 64 + 32 + 512 + 512 + 512 + 512 + 1024 + 1024)
#define ODE_SMEM_B (ODE_SMEM_F * 4)

__device__ __forceinline__ void ode_eval(
    const float* __restrict__ zin, float* __restrict__ kb,
    const float* sW1, const float* sW2, const float* sW3,
    const float* sb1, const float* sb2, const float* sb3,
    float* sh1, float* sh2, int tid)
{
    {   // layer1: 64 out x 32 in, tile 4 out x 2 rows
        const int g0 = (tid & 15) * 4, r0 = (tid >> 4) * 2;
        float a[4][2];
        #pragma unroll
        for (int i = 0; i < 4; i++) { float b = sb1[g0 + i]; a[i][0] = b; a[i][1] = b; }
        #pragma unroll 4
        for (int f = 0; f < LL; f++) {
            float4 w = *(const float4*)(sW1 + f * 64 + g0);
            float2 zv = *(const float2*)(zin + f * 16 + r0);
            float wq[4] = {w.x, w.y, w.z, w.w};
            #pragma unroll
            for (int i = 0; i < 4; i++) {
                a[i][0] = fmaf(wq[i], zv.x, a[i][0]);
                a[i][1] = fmaf(wq[i], zv.y, a[i][1]);
            }
        }
        #pragma unroll
        for (int i = 0; i < 4; i++) {
            sh1[(g0 + i) * 16 + r0]     = tanhf_fast(a[i][0]);
            sh1[(g0 + i) * 16 + r0 + 1] = tanhf_fast(a[i][1]);
        }
    }
    __syncthreads();
    {   // layer2: 64 out x 64 in
        const int g0 = (tid & 15) * 4, r0 = (tid >> 4) * 2;
        float a[4][2];
        #pragma unroll
        for (int i = 0; i < 4; i++) { float b = sb2[g0 + i]; a[i][0] = b; a[i][1] = b; }
        #pragma unroll 4
        for (int f = 0; f < OHH; f++) {
            float4 w = *(const float4*)(sW2 + f * 64 + g0);
            float2 zv = *(const float2*)(sh1 + f * 16 + r0);
            float wq[4] = {w.x, w.y, w.z, w.w};
            #pragma unroll
            for (int i = 0; i < 4; i++) {
                a[i][0] = fmaf(wq[i], zv.x, a[i][0]);
                a[i][1] = fmaf(wq[i], zv.y, a[i][1]);
            }
        }
        #pragma unroll
        for (int i = 0; i < 4; i++) {
            sh2[(g0 + i) * 16 + r0]     = tanhf_fast(a[i][0]);
            sh2[(g0 + i) * 16 + r0 + 1] = tanhf_fast(a[i][1]);
        }
    }
    __syncthreads();
    {   // layer3: 32 out x 64 in, tile 4 out x 1 row
        const int g0 = (tid & 7) * 4, r = tid >> 3;
        float a[4];
        #pragma unroll
        for (int i = 0; i < 4; i++) a[i] = sb3[g0 + i];
        #pragma unroll 4
        for (int f = 0; f < OHH; f++) {
            float4 w = *(const float4*)(sW3 + f * 32 + g0);
            float hv = sh2[f * 16 + r];
            a[0] = fmaf(w.x, hv, a[0]); a[1] = fmaf(w.y, hv, a[1]);
            a[2] = fmaf(w.z, hv, a[2]); a[3] = fmaf(w.w, hv, a[3]);
        }
        #pragma unroll
        for (int i = 0; i < 4; i++) kb[(g0 + i) * 16 + r] = a[i];
    }
    __syncthreads();
}

__global__ void __launch_bounds__(128, 1) ode_kernel(
    const float* __restrict__ W1, const float* __restrict__ b1,
    const float* __restrict__ W2, const float* __restrict__ b2,
    const float* __restrict__ W3, const float* __restrict__ b3)
{
    extern __shared__ float sm[];
    float* sW1 = sm;            // [f][64]
    float* sW2 = sW1 + 2048;
    float* sW3 = sW2 + 4096;    // [f][32]
    float* sb1 = sW3 + 2048;
    float* sb2 = sb1 + 64;
    float* sb3 = sb2 + 64;
    float* zc  = sb3 + 32;      // [32][16]
    float* za  = zc + 512;
    float* zin = za + 512;
    float* kb  = zin + 512;
    float* sh1 = kb + 512;      // [64][16]
    float* sh2 = sh1 + 1024;

    const int tid = threadIdx.x;
    const int row0 = blockIdx.x * 16;

    for (int i = tid; i < OHH * LL; i += 128) {
        int o = i >> 5, f = i & 31;
        sW1[f * 64 + o] = W1[i];
        sW3[o * 32 + f] = W3[f * 64 + o];
    }
    for (int i = tid; i < OHH * OHH; i += 128) {
        int o = i >> 6, f = i & 63;
        sW2[f * 64 + o] = W2[i];
    }
    if (tid < 64) { sb1[tid] = b1[tid]; sb2[tid] = b2[tid]; }
    if (tid < 32) sb3[tid] = b3[tid];
    #pragma unroll
    for (int k = 0; k < 4; k++) {
        int idx = tid + k * 128;
        int l = idx >> 4, r = idx & 15;
        zc[l * 16 + r] = g_z0[(size_t)(row0 + r) * LL + l];
    }
    __syncthreads();

    const float hs = 48.0f / NSTEP;
    for (int s = 0; s < NSTEP; s++) {
        ode_eval(zc, kb, sW1, sW2, sW3, sb1, sb2, sb3, sh1, sh2, tid);   // k1
        #pragma unroll
        for (int k = 0; k < 4; k++) {
            int i = tid + k * 128;
            za[i]  = fmaf(hs / 6.f, kb[i], zc[i]);
            zin[i] = fmaf(hs * 0.5f, kb[i], zc[i]);
        }
        __syncthreads();
        ode_eval(zin, kb, sW1, sW2, sW3, sb1, sb2, sb3, sh1, sh2, tid);  // k2
        #pragma unroll
        for (int k = 0; k < 4; k++) {
            int i = tid + k * 128;
            za[i]  = fmaf(hs / 3.f, kb[i], za[i]);
            zin[i] = fmaf(hs * 0.5f, kb[i], zc[i]);
        }
        __syncthreads();
        ode_eval(zin, kb, sW1, sW2, sW3, sb1, sb2, sb3, sh1, sh2, tid);  // k3
        #pragma unroll
        for (int k = 0; k < 4; k++) {
            int i = tid + k * 128;
            za[i]  = fmaf(hs / 3.f, kb[i], za[i]);
            zin[i] = fmaf(hs, kb[i], zc[i]);
        }
        __syncthreads();
        ode_eval(zin, kb, sW1, sW2, sW3, sb1, sb2, sb3, sh1, sh2, tid);  // k4
        #pragma unroll
        for (int k = 0; k < 4; k++) {
            int i = tid + k * 128;
            zc[i] = fmaf(hs / 6.f, kb[i], za[i]);
        }
        __syncthreads();
    }

    #pragma unroll
    for (int k = 0; k < 4; k++) {
        int idx = tid + k * 128;
        int l = idx >> 4, r = idx & 15;
        g_zf[(size_t)(row0 + r) * LL + l] = zc[l * 16 + r];
    }
}

// =====================================================================
// Decoder: one warp per row
// =====================================================================
__global__ void __launch_bounds__(256) dec_kernel(
    const float* __restrict__ W1, const float* __restrict__ b1,
    const float* __restrict__ W2, const float* __restrict__ b2,
    float* __restrict__ out)
{
    __shared__ float sz[8][32];
    const int w = threadIdx.x >> 5, l = threadIdx.x & 31;
    const int row = blockIdx.x * 8 + w;
    sz[w][l] = g_zf[(size_t)row * LL + l];
    __syncwarp();
    float a0 = b1[l], a1 = b1[l + 32];
    #pragma unroll 8
    for (int f = 0; f < LL; f++) {
        float zv = sz[w][f];
        a0 = fmaf(__ldg(W1 + l * LL + f), zv, a0);
        a1 = fmaf(__ldg(W1 + (l + 32) * LL + f), zv, a1);
    }
    a0 = fmaxf(a0, 0.f); a1 = fmaxf(a1, 0.f);
    float p = a0 * __ldg(W2 + l) + a1 * __ldg(W2 + l + 32);
    #pragma unroll
    for (int off = 16; off; off >>= 1) p += __shfl_down_sync(0xffffffffu, p, off);
    if (l == 0) out[row] = p + b2[0];
}

__global__ void __launch_bounds__(1024) kl_kernel(float* __restrict__ out)
{
    __shared__ float s[1024];
    const int t = threadIdx.x;
    s[t] = g_klrow[t] + g_klrow[t + 1024];
    __syncthreads();
    for (int o = 512; o; o >>= 1) {
        if (t < o) s[t] += s[t + o];
        __syncthreads();
    }
    if (t == 0) out[BB] = -0.5f * s[0] / ((float)BB * (float)LL);
}

// =====================================================================
extern "C" void kernel_launch(void* const* d_in, const int* in_sizes, int n_in,
                              void* d_out, int out_size)
{
    const float* values = (const float*)d_in[1];
    const float* maskp  = (const float*)d_in[2];
    const int*   seql   = (const int*)d_in[3];
    const float* eps    = (const float*)d_in[4];
    const float* W_ih   = (const float*)d_in[5];
    const float* W_hh   = (const float*)d_in[6];
    const float* b_ih   = (const float*)d_in[7];
    const float* b_hh   = (const float*)d_in[8];
    const float* W_z0   = (const float*)d_in[9];
    const float* b_z0   = (const float*)d_in[10];
    const float* oW1    = (const float*)d_in[11];
    const float* ob1    = (const float*)d_in[12];
    const float* oW2    = (const float*)d_in[13];
    const float* ob2    = (const float*)d_in[14];
    const float* oW3    = (const float*)d_in[15];
    const float* ob3    = (const float*)d_in[16];
    const float* dW1    = (const float*)d_in[17];
    const float* db1    = (const float*)d_in[18];
    const float* dW2    = (const float*)d_in[19];
    const float* db2    = (const float*)d_in[20];
    float* out = (float*)d_out;

    cudaFuncSetAttribute(xp_kernel,  cudaFuncAttributeMaxDynamicSharedMemorySize, XP_SMEM_B);
    cudaFuncSetAttribute(gru_kernel, cudaFuncAttributeMaxDynamicSharedMemorySize, GRU_SMEM_B);
    cudaFuncSetAttribute(ode_kernel, cudaFuncAttributeMaxDynamicSharedMemorySize, ODE_SMEM_B);

    xp_kernel<<<dim3(16, 256), 256, XP_SMEM_B>>>(values, maskp, W_ih, b_ih);
    gru_kernel<<<128, 256, GRU_SMEM_B>>>(seql, W_hh, b_hh);
    z0_kernel<<<256, 256>>>(W_z0, b_z0, eps);
    ode_kernel<<<128, 128, ODE_SMEM_B>>>(oW1, ob1, oW2, ob2, oW3, ob3);
    dec_kernel<<<256, 256>>>(dW1, db1, dW2, db2, out);
    kl_kernel<<<1, 1024>>>(out);
}

// round 6
// speedup vs baseline: 1.7501x; 1.7501x over previous
#include <cuda_runtime.h>
#include <cuda_fp16.h>
#include <cstdint>

#define BB 2048
#define TT 256
#define NVV 32
#define HH 64
#define GG 192
#define LL 32
#define OHH 64

__device__ float g_h[BB * HH];
__device__ float g_z0[BB * LL];
__device__ float g_zf[BB * LL];
__device__ float g_klrow[BB];
// xp[t][g][b] fp16, t = scan step (time-reversed). 201 MB scratch.
__device__ __half g_xph[(size_t)TT * GG * BB];

__device__ __forceinline__ float sigf(float x) {
    return __fdividef(1.f, 1.f + __expf(-x));
}
__device__ __forceinline__ float tanhf_fast(float x) {
    return 1.f - __fdividef(2.f, __expf(2.f * x) + 1.f);
}

// =====================================================================
// xp GEMM via fp16 tensor cores, fp32 accumulate.
// xp[t][g][b] = b_ih[g] + sum_f W_ih[g][f] * x[b][255-t][f]
// grid (16 b-blocks of 128, 256 t) x 256 threads.
// mma.m16n8k16: A = W (rows=g, cols=f, row-major), B = x (k=f, n=b, col-major)
// warp layout: wg=w>>2 covers 96 g, wb=w&3 covers 32 b.
// =====================================================================
__global__ void __launch_bounds__(256) xp_kernel(
    const float* __restrict__ values, const float* __restrict__ maskp,
    const float* __restrict__ W_ih, const float* __restrict__ b_ih)
{
    __shared__ __half sW[192 * 72];   // [g][f], stride 72 (conflict-free)
    __shared__ __half sX[128 * 72];   // [b][f], stride 72

    const int tid = threadIdx.x;
    const int bb = blockIdx.x;
    const int t = blockIdx.y;
    const int tt = TT - 1 - t;
    const int bbase = bb * 128;

    for (int i = tid; i < GG * HH; i += 256) {
        int g = i >> 6, f = i & 63;
        sW[g * 72 + f] = __float2half(W_ih[i]);
    }
    for (int i = tid; i < 128 * HH; i += 256) {
        int bl = i >> 6, f = i & 63;
        size_t base = (size_t)(bbase + bl) * TT * NVV + (size_t)tt * NVV;
        float v = (f < NVV) ? values[base + f] : maskp[base + f - NVV];
        sX[bl * 72 + f] = __float2half(v);
    }
    __syncthreads();

    const int w = tid >> 5, l = tid & 31;
    const int wg = w >> 2;            // 0..1 -> 96 g each
    const int wb = w & 3;             // 0..3 -> 32 b each
    const int l4 = l >> 2;            // 0..7
    const int l2 = (l & 3) * 2;       // 0,2,4,6

    #pragma unroll
    for (int gt = 0; gt < 6; gt++) {
        const int g0 = wg * 96 + gt * 16;
        uint32_t a[4][4];
        #pragma unroll
        for (int kk = 0; kk < 4; kk++) {
            const __half* p = &sW[(g0 + l4) * 72 + kk * 16 + l2];
            a[kk][0] = *(const uint32_t*)(p);
            a[kk][1] = *(const uint32_t*)(p + 8 * 72);
            a[kk][2] = *(const uint32_t*)(p + 8);
            a[kk][3] = *(const uint32_t*)(p + 8 * 72 + 8);
        }
        const float bias0 = __ldg(b_ih + g0 + l4);
        const float bias1 = __ldg(b_ih + g0 + 8 + l4);

        #pragma unroll
        for (int bt = 0; bt < 4; bt++) {
            const int b0 = wb * 32 + bt * 8;
            float c0 = bias0, c1 = bias0, c2 = bias1, c3 = bias1;
            #pragma unroll
            for (int kk = 0; kk < 4; kk++) {
                const __half* bp = &sX[(b0 + l4) * 72 + kk * 16 + l2];
                uint32_t br0 = *(const uint32_t*)(bp);
                uint32_t br1 = *(const uint32_t*)(bp + 8);
                asm volatile(
                    "mma.sync.aligned.m16n8k16.row.col.f32.f16.f16.f32 "
                    "{%0,%1,%2,%3}, {%4,%5,%6,%7}, {%8,%9}, {%0,%1,%2,%3};\n"
                    : "+f"(c0), "+f"(c1), "+f"(c2), "+f"(c3)
                    : "r"(a[kk][0]), "r"(a[kk][1]), "r"(a[kk][2]), "r"(a[kk][3]),
                      "r"(br0), "r"(br1));
            }
            const int gg = g0 + l4;
            const int bglob = bbase + b0 + l2;
            size_t base = ((size_t)t * GG + gg) * BB + bglob;
            *(__half2*)(g_xph + base) = __floats2half2_rn(c0, c1);
            *(__half2*)(g_xph + base + (size_t)8 * BB) = __floats2half2_rn(c2, c3);
        }
    }
}

// =====================================================================
// GRU scan: 128 CTAs x 256 thr, 16 rows/CTA. Only W_hh matvec (fp32).
// Thread: j = tid>>2 (0..63), rows r0 = (tid&3)*4 .. +3.
// Weights packed [f][j][4] = {R,Z,N,pad}: one LDS.128 per f.
// Per f per thread: 2 LDS.128 + 12 FFMA.
// =====================================================================
#define GRU_SMEM_F (64 * 256 + 64 * 20)
#define GRU_SMEM_B (GRU_SMEM_F * 4)

__global__ void __launch_bounds__(256, 1) gru_kernel(
    const int* __restrict__ seqlen,
    const float* __restrict__ W_hh, const float* __restrict__ b_hh)
{
    extern __shared__ float sm[];
    float* sW = sm;                 // [f][j*4 + gate]
    float* sh = sW + 64 * 256;      // [f][20]

    const int tid  = threadIdx.x;
    const int row0 = blockIdx.x * 16;

    for (int i = tid; i < GG * HH; i += 256) {
        int g = i >> 6, f = i & 63;
        int j = g & 63, gate = g >> 6;
        sW[f * 256 + j * 4 + gate] = W_hh[i];
    }
    for (int i = tid; i < 1280; i += 256) sh[i] = 0.f;

    const int j  = tid >> 2;       // 0..63
    const int r0 = (tid & 3) * 4;  // 0,4,8,12

    const float bhr = __ldg(b_hh + j);
    const float bhz = __ldg(b_hh + 64 + j);
    const float bhn = __ldg(b_hh + 128 + j);

    int seqr[4];
    #pragma unroll
    for (int c = 0; c < 4; c++) seqr[c] = __ldg(seqlen + row0 + r0 + c);

    float hprev[4] = {0.f, 0.f, 0.f, 0.f};

    // xp loads for step 0 (fp16, 4 rows each gate)
    const size_t xoff = (size_t)row0 + r0;
    uint2 xr = *(const uint2*)(g_xph + (size_t)j * BB + xoff);
    uint2 xz = *(const uint2*)(g_xph + (size_t)(j + 64) * BB + xoff);
    uint2 xn = *(const uint2*)(g_xph + (size_t)(j + 128) * BB + xoff);
    __syncthreads();

    for (int t = 0; t < TT; t++) {
        uint2 pr, pz, pn;
        if (t + 1 < TT) {
            const __half* nb = g_xph + ((size_t)(t + 1) * GG + j) * BB + xoff;
            pr = *(const uint2*)(nb);
            pz = *(const uint2*)(nb + (size_t)64 * BB);
            pn = *(const uint2*)(nb + (size_t)128 * BB);
        }

        // unpack fp16 xp -> fp32
        float2 xr01 = __half22float2(*(__half2*)&xr.x);
        float2 xr23 = __half22float2(*(__half2*)&xr.y);
        float2 xz01 = __half22float2(*(__half2*)&xz.x);
        float2 xz23 = __half22float2(*(__half2*)&xz.y);
        float2 xn01 = __half22float2(*(__half2*)&xn.x);
        float2 xn23 = __half22float2(*(__half2*)&xn.y);

        float aR[4] = {xr01.x + bhr, xr01.y + bhr, xr23.x + bhr, xr23.y + bhr};
        float aZ[4] = {xz01.x + bhz, xz01.y + bhz, xz23.x + bhz, xz23.y + bhz};
        float aN[4] = {bhn, bhn, bhn, bhn};
        float fx[4] = {xn01.x, xn01.y, xn23.x, xn23.y};

        const float* wj = sW + j * 4;
        const float* hr = sh + r0;
        #pragma unroll 8
        for (int f = 0; f < HH; f++) {
            float4 w  = *(const float4*)(wj + f * 256);
            float4 hv = *(const float4*)(hr + f * 20);
            float hq[4] = {hv.x, hv.y, hv.z, hv.w};
            #pragma unroll
            for (int c = 0; c < 4; c++) {
                aR[c] = fmaf(w.x, hq[c], aR[c]);
                aZ[c] = fmaf(w.y, hq[c], aZ[c]);
                aN[c] = fmaf(w.z, hq[c], aN[c]);
            }
        }

        float hnew[4];
        #pragma unroll
        for (int c = 0; c < 4; c++) {
            float rr = sigf(aR[c]);
            float zz = sigf(aZ[c]);
            float nn = tanhf_fast(fx[c] + rr * aN[c]);
            float hn = (1.f - zz) * nn + zz * hprev[c];
            hnew[c] = (t < seqr[c]) ? hn : hprev[c];
            hprev[c] = hnew[c];
        }
        __syncthreads();
        *(float4*)(sh + j * 20 + r0) = make_float4(hnew[0], hnew[1], hnew[2], hnew[3]);
        xr = pr; xz = pz; xn = pn;
        __syncthreads();
    }

    #pragma unroll
    for (int c = 0; c < 4; c++)
        g_h[(size_t)(row0 + r0 + c) * HH + j] = hprev[c];
}

// =====================================================================
// z0: one warp per row (8 warps/CTA, 256 CTAs)
// =====================================================================
__global__ void __launch_bounds__(256) z0_kernel(
    const float* __restrict__ Wz0, const float* __restrict__ bz0,
    const float* __restrict__ eps)
{
    __shared__ float sH[8][64];
    const int w = threadIdx.x >> 5, l = threadIdx.x & 31;
    const int row = blockIdx.x * 8 + w;
    sH[w][l]      = g_h[(size_t)row * HH + l];
    sH[w][l + 32] = g_h[(size_t)row * HH + l + 32];
    __syncwarp();
    float m = bz0[l], lv = bz0[l + 32];
    #pragma unroll 8
    for (int f = 0; f < HH; f++) {
        float hf = sH[w][f];
        m  = fmaf(__ldg(Wz0 + l * HH + f), hf, m);
        lv = fmaf(__ldg(Wz0 + (l + 32) * HH + f), hf, lv);
    }
    g_z0[(size_t)row * LL + l] = m + eps[(size_t)row * LL + l] * __expf(0.5f * lv);
    float kterm = 1.f + lv - m * m - __expf(lv);
    #pragma unroll
    for (int off = 16; off; off >>= 1) kterm += __shfl_down_sync(0xffffffffu, kterm, off);
    if (l == 0) g_klrow[row] = kterm;
}

// =====================================================================
// ODE: fixed-step RK4, NSTEP steps over [0,48].
// 128 CTAs x 256 thr, 16 rows/CTA (8 warps -> latency hidden).
// =====================================================================
#define NSTEP 8
#define ODE_SMEM_F (2048 + 4096 + 2048 + 64 + 64 + 32 + 512 + 512 + 512 + 512 + 1024 + 1024)
#define ODE_SMEM_B (ODE_SMEM_F * 4)

__device__ __forceinline__ void ode_eval(
    const float* __restrict__ zin, float* __restrict__ kb,
    const float* sW1, const float* sW2, const float* sW3,
    const float* sb1, const float* sb2, const float* sb3,
    float* sh1, float* sh2, int tid)
{
    {   // layer1: 64 out x 32 in; thread: 2 out x 2 rows
        const int o0 = (tid & 31) * 2, r0 = (tid >> 5) * 2;
        float a00 = sb1[o0], a01 = a00, a10 = sb1[o0 + 1], a11 = a10;
        #pragma unroll 8
        for (int f = 0; f < LL; f++) {
            float2 w  = *(const float2*)(sW1 + f * 64 + o0);
            float2 zv = *(const float2*)(zin + f * 16 + r0);
            a00 = fmaf(w.x, zv.x, a00); a01 = fmaf(w.x, zv.y, a01);
            a10 = fmaf(w.y, zv.x, a10); a11 = fmaf(w.y, zv.y, a11);
        }
        sh1[o0 * 16 + r0]           = tanhf_fast(a00);
        sh1[o0 * 16 + r0 + 1]       = tanhf_fast(a01);
        sh1[(o0 + 1) * 16 + r0]     = tanhf_fast(a10);
        sh1[(o0 + 1) * 16 + r0 + 1] = tanhf_fast(a11);
    }
    __syncthreads();
    {   // layer2: 64 out x 64 in
        const int o0 = (tid & 31) * 2, r0 = (tid >> 5) * 2;
        float a00 = sb2[o0], a01 = a00, a10 = sb2[o0 + 1], a11 = a10;
        #pragma unroll 8
        for (int f = 0; f < OHH; f++) {
            float2 w  = *(const float2*)(sW2 + f * 64 + o0);
            float2 zv = *(const float2*)(sh1 + f * 16 + r0);
            a00 = fmaf(w.x, zv.x, a00); a01 = fmaf(w.x, zv.y, a01);
            a10 = fmaf(w.y, zv.x, a10); a11 = fmaf(w.y, zv.y, a11);
        }
        sh2[o0 * 16 + r0]           = tanhf_fast(a00);
        sh2[o0 * 16 + r0 + 1]       = tanhf_fast(a01);
        sh2[(o0 + 1) * 16 + r0]     = tanhf_fast(a10);
        sh2[(o0 + 1) * 16 + r0 + 1] = tanhf_fast(a11);
    }
    __syncthreads();
    {   // layer3: 32 out x 64 in; thread: 2 out x 1 row
        const int o0 = (tid & 15) * 2, r = tid >> 4;
        float a0 = sb3[o0], a1 = sb3[o0 + 1];
        #pragma unroll 8
        for (int f = 0; f < OHH; f++) {
            float2 w = *(const float2*)(sW3 + f * 32 + o0);
            float hv = sh2[f * 16 + r];
            a0 = fmaf(w.x, hv, a0);
            a1 = fmaf(w.y, hv, a1);
        }
        kb[o0 * 16 + r]       = a0;
        kb[(o0 + 1) * 16 + r] = a1;
    }
    __syncthreads();
}

__global__ void __launch_bounds__(256, 1) ode_kernel(
    const float* __restrict__ W1, const float* __restrict__ b1,
    const float* __restrict__ W2, const float* __restrict__ b2,
    const float* __restrict__ W3, const float* __restrict__ b3)
{
    extern __shared__ float sm[];
    float* sW1 = sm;            // [f][64]
    float* sW2 = sW1 + 2048;
    float* sW3 = sW2 + 4096;    // [f][32]
    float* sb1 = sW3 + 2048;
    float* sb2 = sb1 + 64;
    float* sb3 = sb2 + 64;
    float* zc  = sb3 + 32;      // [32][16]
    float* za  = zc + 512;
    float* zin = za + 512;
    float* kb  = zin + 512;
    float* sh1 = kb + 512;      // [64][16]
    float* sh2 = sh1 + 1024;

    const int tid = threadIdx.x;
    const int row0 = blockIdx.x * 16;

    for (int i = tid; i < OHH * LL; i += 256) {
        int o = i >> 5, f = i & 31;
        sW1[f * 64 + o] = W1[i];
        sW3[o * 32 + f] = W3[f * 64 + o];
    }
    for (int i = tid; i < OHH * OHH; i += 256) {
        int o = i >> 6, f = i & 63;
        sW2[f * 64 + o] = W2[i];
    }
    if (tid < 64) { sb1[tid] = b1[tid]; sb2[tid] = b2[tid]; }
    if (tid < 32) sb3[tid] = b3[tid];
    #pragma unroll
    for (int k = 0; k < 2; k++) {
        int idx = tid + k * 256;
        int l = idx >> 4, r = idx & 15;
        zc[l * 16 + r] = g_z0[(size_t)(row0 + r) * LL + l];
    }
    __syncthreads();

    const float hs = 48.0f / NSTEP;
    for (int s = 0; s < NSTEP; s++) {
        ode_eval(zc, kb, sW1, sW2, sW3, sb1, sb2, sb3, sh1, sh2, tid);   // k1
        #pragma unroll
        for (int k = 0; k < 2; k++) {
            int i = tid + k * 256;
            za[i]  = fmaf(hs / 6.f, kb[i], zc[i]);
            zin[i] = fmaf(hs * 0.5f, kb[i], zc[i]);
        }
        __syncthreads();
        ode_eval(zin, kb, sW1, sW2, sW3, sb1, sb2, sb3, sh1, sh2, tid);  // k2
        #pragma unroll
        for (int k = 0; k < 2; k++) {
            int i = tid + k * 256;
            za[i]  = fmaf(hs / 3.f, kb[i], za[i]);
            zin[i] = fmaf(hs * 0.5f, kb[i], zc[i]);
        }
        __syncthreads();
        ode_eval(zin, kb, sW1, sW2, sW3, sb1, sb2, sb3, sh1, sh2, tid);  // k3
        #pragma unroll
        for (int k = 0; k < 2; k++) {
            int i = tid + k * 256;
            za[i]  = fmaf(hs / 3.f, kb[i], za[i]);
            zin[i] = fmaf(hs, kb[i], zc[i]);
        }
        __syncthreads();
        ode_eval(zin, kb, sW1, sW2, sW3, sb1, sb2, sb3, sh1, sh2, tid);  // k4
        #pragma unroll
        for (int k = 0; k < 2; k++) {
            int i = tid + k * 256;
            zc[i] = fmaf(hs / 6.f, kb[i], za[i]);
        }
        __syncthreads();
    }

    #pragma unroll
    for (int k = 0; k < 2; k++) {
        int idx = tid + k * 256;
        int l = idx >> 4, r = idx & 15;
        g_zf[(size_t)(row0 + r) * LL + l] = zc[l * 16 + r];
    }
}

// =====================================================================
// Decoder: one warp per row
// =====================================================================
__global__ void __launch_bounds__(256) dec_kernel(
    const float* __restrict__ W1, const float* __restrict__ b1,
    const float* __restrict__ W2, const float* __restrict__ b2,
    float* __restrict__ out)
{
    __shared__ float sz[8][32];
    const int w = threadIdx.x >> 5, l = threadIdx.x & 31;
    const int row = blockIdx.x * 8 + w;
    sz[w][l] = g_zf[(size_t)row * LL + l];
    __syncwarp();
    float a0 = b1[l], a1 = b1[l + 32];
    #pragma unroll 8
    for (int f = 0; f < LL; f++) {
        float zv = sz[w][f];
        a0 = fmaf(__ldg(W1 + l * LL + f), zv, a0);
        a1 = fmaf(__ldg(W1 + (l + 32) * LL + f), zv, a1);
    }
    a0 = fmaxf(a0, 0.f); a1 = fmaxf(a1, 0.f);
    float p = a0 * __ldg(W2 + l) + a1 * __ldg(W2 + l + 32);
    #pragma unroll
    for (int off = 16; off; off >>= 1) p += __shfl_down_sync(0xffffffffu, p, off);
    if (l == 0) out[row] = p + b2[0];
}

__global__ void __launch_bounds__(1024) kl_kernel(float* __restrict__ out)
{
    __shared__ float s[1024];
    const int t = threadIdx.x;
    s[t] = g_klrow[t] + g_klrow[t + 1024];
    __syncthreads();
    for (int o = 512; o; o >>= 1) {
        if (t < o) s[t] += s[t + o];
        __syncthreads();
    }
    if (t == 0) out[BB] = -0.5f * s[0] / ((float)BB * (float)LL);
}

// =====================================================================
extern "C" void kernel_launch(void* const* d_in, const int* in_sizes, int n_in,
                              void* d_out, int out_size)
{
    const float* values = (const float*)d_in[1];
    const float* maskp  = (const float*)d_in[2];
    const int*   seql   = (const int*)d_in[3];
    const float* eps    = (const float*)d_in[4];
    const float* W_ih   = (const float*)d_in[5];
    const float* W_hh   = (const float*)d_in[6];
    const float* b_ih   = (const float*)d_in[7];
    const float* b_hh   = (const float*)d_in[8];
    const float* W_z0   = (const float*)d_in[9];
    const float* b_z0   = (const float*)d_in[10];
    const float* oW1    = (const float*)d_in[11];
    const float* ob1    = (const float*)d_in[12];
    const float* oW2    = (const float*)d_in[13];
    const float* ob2    = (const float*)d_in[14];
    const float* oW3    = (const float*)d_in[15];
    const float* ob3    = (const float*)d_in[16];
    const float* dW1    = (const float*)d_in[17];
    const float* db1    = (const float*)d_in[18];
    const float* dW2    = (const float*)d_in[19];
    const float* db2    = (const float*)d_in[20];
    float* out = (float*)d_out;

    cudaFuncSetAttribute(gru_kernel, cudaFuncAttributeMaxDynamicSharedMemorySize, GRU_SMEM_B);
    cudaFuncSetAttribute(ode_kernel, cudaFuncAttributeMaxDynamicSharedMemorySize, ODE_SMEM_B);

    xp_kernel<<<dim3(16, 256), 256>>>(values, maskp, W_ih, b_ih);
    gru_kernel<<<128, 256, GRU_SMEM_B>>>(seql, W_hh, b_hh);
    z0_kernel<<<256, 256>>>(W_z0, b_z0, eps);
    ode_kernel<<<128, 256, ODE_SMEM_B>>>(oW1, ob1, oW2, ob2, oW3, ob3);
    dec_kernel<<<256, 256>>>(dW1, db1, dW2, db2, out);
    kl_kernel<<<1, 1024>>>(out);
}

// round 7
// speedup vs baseline: 2.5096x; 1.4340x over previous
#include <cuda_runtime.h>
#include <cuda_fp16.h>
#include <cstdint>

#define BB 2048
#define TT 256
#define NVV 32
#define HH 64
#define GG 192
#define LL 32
#define OHH 64

__device__ float g_h[BB * HH];
__device__ float g_z0[BB * LL];
__device__ float g_zf[BB * LL];
__device__ float g_klrow[BB];
// xp[t][g][b] fp16, t = scan step (time-reversed). 201 MB scratch.
__device__ __half g_xph[(size_t)TT * GG * BB];

__device__ __forceinline__ float sigf(float x) {
    return __fdividef(1.f, 1.f + __expf(-x));
}
__device__ __forceinline__ float tanhf_fast(float x) {
    return 1.f - __fdividef(2.f, __expf(2.f * x) + 1.f);
}

// =====================================================================
// xp GEMM via fp16 tensor cores, fp32 accumulate. (unchanged from R5)
// =====================================================================
__global__ void __launch_bounds__(256) xp_kernel(
    const float* __restrict__ values, const float* __restrict__ maskp,
    const float* __restrict__ W_ih, const float* __restrict__ b_ih)
{
    __shared__ __half sW[192 * 72];
    __shared__ __half sX[128 * 72];

    const int tid = threadIdx.x;
    const int bb = blockIdx.x;
    const int t = blockIdx.y;
    const int tt = TT - 1 - t;
    const int bbase = bb * 128;

    for (int i = tid; i < GG * HH; i += 256) {
        int g = i >> 6, f = i & 63;
        sW[g * 72 + f] = __float2half(W_ih[i]);
    }
    for (int i = tid; i < 128 * HH; i += 256) {
        int bl = i >> 6, f = i & 63;
        size_t base = (size_t)(bbase + bl) * TT * NVV + (size_t)tt * NVV;
        float v = (f < NVV) ? values[base + f] : maskp[base + f - NVV];
        sX[bl * 72 + f] = __float2half(v);
    }
    __syncthreads();

    const int w = tid >> 5, l = tid & 31;
    const int wg = w >> 2;
    const int wb = w & 3;
    const int l4 = l >> 2;
    const int l2 = (l & 3) * 2;

    #pragma unroll
    for (int gt = 0; gt < 6; gt++) {
        const int g0 = wg * 96 + gt * 16;
        uint32_t a[4][4];
        #pragma unroll
        for (int kk = 0; kk < 4; kk++) {
            const __half* p = &sW[(g0 + l4) * 72 + kk * 16 + l2];
            a[kk][0] = *(const uint32_t*)(p);
            a[kk][1] = *(const uint32_t*)(p + 8 * 72);
            a[kk][2] = *(const uint32_t*)(p + 8);
            a[kk][3] = *(const uint32_t*)(p + 8 * 72 + 8);
        }
        const float bias0 = __ldg(b_ih + g0 + l4);
        const float bias1 = __ldg(b_ih + g0 + 8 + l4);

        #pragma unroll
        for (int bt = 0; bt < 4; bt++) {
            const int b0 = wb * 32 + bt * 8;
            float c0 = bias0, c1 = bias0, c2 = bias1, c3 = bias1;
            #pragma unroll
            for (int kk = 0; kk < 4; kk++) {
                const __half* bp = &sX[(b0 + l4) * 72 + kk * 16 + l2];
                uint32_t br0 = *(const uint32_t*)(bp);
                uint32_t br1 = *(const uint32_t*)(bp + 8);
                asm volatile(
                    "mma.sync.aligned.m16n8k16.row.col.f32.f16.f16.f32 "
                    "{%0,%1,%2,%3}, {%4,%5,%6,%7}, {%8,%9}, {%0,%1,%2,%3};\n"
                    : "+f"(c0), "+f"(c1), "+f"(c2), "+f"(c3)
                    : "r"(a[kk][0]), "r"(a[kk][1]), "r"(a[kk][2]), "r"(a[kk][3]),
                      "r"(br0), "r"(br1));
            }
            const int gg = g0 + l4;
            const int bglob = bbase + b0 + l2;
            size_t base = ((size_t)t * GG + gg) * BB + bglob;
            *(__half2*)(g_xph + base) = __floats2half2_rn(c0, c1);
            *(__half2*)(g_xph + base + (size_t)8 * BB) = __floats2half2_rn(c2, c3);
        }
    }
}

// =====================================================================
// GRU scan with split-fp16 tensor-core h-matvec (fp32-equivalent accuracy).
// 128 CTAs x 256 thr (8 warps), 16 rows/CTA.
// Warp w: m-tiles {mw, mw+4, mw+8} (R/Z/N of j-range 16mw..16mw+15),
//         n-tile nt=w>>2 (rows 8nt..8nt+7).
// Lane's C fragments ARE its gate pre-activations; h state in registers.
// h exchanged via double-buffered SMEM tile as fp16 hi/lo; 1 sync/step.
// D = Whi@hhi + Whi@hlo + Wlo@hhi (fp32 accum) => ~2e-7 matvec error.
// =====================================================================
#define GRU_SMEM_B (192*72*2*2 + 2*2*16*72*2)   // Whi,Wlo | h[2buf][2split][16][72]

__global__ void __launch_bounds__(256, 1) gru_kernel(
    const int* __restrict__ seqlen,
    const float* __restrict__ W_hh, const float* __restrict__ b_hh)
{
    extern __shared__ char smem[];
    __half* sWhi = (__half*)smem;            // [192][72]
    __half* sWlo = sWhi + 192 * 72;          // [192][72]
    __half* sH   = sWlo + 192 * 72;          // [2][2][16][72]
#define SH(buf, sp, n, k) sH[((((buf) * 2 + (sp)) * 16) + (n)) * 72 + (k)]

    const int tid  = threadIdx.x;
    const int row0 = blockIdx.x * 16;

    // stage split weights
    for (int i = tid; i < GG * HH; i += 256) {
        int g = i >> 6, k = i & 63;
        float wv = W_hh[i];
        __half hi = __float2half(wv);
        __half lo = __float2half(wv - __half2float(hi));
        sWhi[g * 72 + k] = hi;
        sWlo[g * 72 + k] = lo;
    }
    // zero h buffers
    for (int i = tid; i < 2 * 2 * 16 * 72; i += 256) sH[i] = __float2half(0.f);
    __syncthreads();

    const int l  = tid & 31;
    const int w  = tid >> 5;
    const int mw = w & 3;        // j-range 16mw..+15
    const int nt = w >> 2;       // rows 8nt..+7
    const int r  = l >> 2;       // 0..7
    const int cq = (l & 3) * 2;  // 0,2,4,6

    // A fragments (static): [mt][kt][4]  mt: 0=R,1=Z,2=N
    uint32_t Ahi[3][4][4], Alo[3][4][4];
    #pragma unroll
    for (int mt = 0; mt < 3; mt++) {
        const int g0 = 16 * mw + 64 * mt;
        #pragma unroll
        for (int kt = 0; kt < 4; kt++) {
            const int k0 = kt * 16 + cq;
            Ahi[mt][kt][0] = *(const uint32_t*)&sWhi[(g0 + r) * 72 + k0];
            Ahi[mt][kt][1] = *(const uint32_t*)&sWhi[(g0 + r + 8) * 72 + k0];
            Ahi[mt][kt][2] = *(const uint32_t*)&sWhi[(g0 + r) * 72 + k0 + 8];
            Ahi[mt][kt][3] = *(const uint32_t*)&sWhi[(g0 + r + 8) * 72 + k0 + 8];
            Alo[mt][kt][0] = *(const uint32_t*)&sWlo[(g0 + r) * 72 + k0];
            Alo[mt][kt][1] = *(const uint32_t*)&sWlo[(g0 + r + 8) * 72 + k0];
            Alo[mt][kt][2] = *(const uint32_t*)&sWlo[(g0 + r) * 72 + k0 + 8];
            Alo[mt][kt][3] = *(const uint32_t*)&sWlo[(g0 + r + 8) * 72 + k0 + 8];
        }
    }

    const int j0 = 16 * mw + r;
    const int j1 = j0 + 8;
    const int n0 = 8 * nt + cq;      // local rows n0, n0+1
    const float bhr0 = __ldg(b_hh + j0),        bhr1 = __ldg(b_hh + j1);
    const float bhz0 = __ldg(b_hh + 64 + j0),   bhz1 = __ldg(b_hh + 64 + j1);
    const float bhn0 = __ldg(b_hh + 128 + j0),  bhn1 = __ldg(b_hh + 128 + j1);
    const int seq0 = __ldg(seqlen + row0 + n0);
    const int seq1 = __ldg(seqlen + row0 + n0 + 1);

    // h state in registers: e0=(j0,n0) e1=(j0,n0+1) e2=(j1,n0) e3=(j1,n0+1)
    float hp[4] = {0.f, 0.f, 0.f, 0.f};

    // xp for step 0
    const size_t xo = (size_t)row0 + n0;
    __half2 cR0 = *(const __half2*)&g_xph[(size_t)(j0)       * BB + xo];
    __half2 cR1 = *(const __half2*)&g_xph[(size_t)(j1)       * BB + xo];
    __half2 cZ0 = *(const __half2*)&g_xph[(size_t)(j0 + 64)  * BB + xo];
    __half2 cZ1 = *(const __half2*)&g_xph[(size_t)(j1 + 64)  * BB + xo];
    __half2 cN0 = *(const __half2*)&g_xph[(size_t)(j0 + 128) * BB + xo];
    __half2 cN1 = *(const __half2*)&g_xph[(size_t)(j1 + 128) * BB + xo];
    __syncthreads();

    for (int t = 0; t < TT; t++) {
        const int buf = t & 1;
        __half2 pR0, pR1, pZ0, pZ1, pN0, pN1;
        if (t + 1 < TT) {
            const __half* nb = g_xph + (size_t)(t + 1) * GG * BB + xo;
            pR0 = *(const __half2*)&nb[(size_t)(j0)       * BB];
            pR1 = *(const __half2*)&nb[(size_t)(j1)       * BB];
            pZ0 = *(const __half2*)&nb[(size_t)(j0 + 64)  * BB];
            pZ1 = *(const __half2*)&nb[(size_t)(j1 + 64)  * BB];
            pN0 = *(const __half2*)&nb[(size_t)(j0 + 128) * BB];
            pN1 = *(const __half2*)&nb[(size_t)(j1 + 128) * BB];
        }

        // B fragments from h SMEM (hi & lo)
        uint32_t bhi[4][2], blo[4][2];
        const int bn = 8 * nt + r;   // B-frag row index uses l>>2
        #pragma unroll
        for (int kt = 0; kt < 4; kt++) {
            const int k0 = kt * 16 + cq;
            bhi[kt][0] = *(const uint32_t*)&SH(buf, 0, bn, k0);
            bhi[kt][1] = *(const uint32_t*)&SH(buf, 0, bn, k0 + 8);
            blo[kt][0] = *(const uint32_t*)&SH(buf, 1, bn, k0);
            blo[kt][1] = *(const uint32_t*)&SH(buf, 1, bn, k0 + 8);
        }

        // accumulators init: C = xp + b_hh (R,Z); N: b_hh only
        float2 fR0 = __half22float2(cR0), fR1 = __half22float2(cR1);
        float2 fZ0 = __half22float2(cZ0), fZ1 = __half22float2(cZ1);
        float2 fN0 = __half22float2(cN0), fN1 = __half22float2(cN1);
        float acc[3][4];
        acc[0][0] = fR0.x + bhr0; acc[0][1] = fR0.y + bhr0;
        acc[0][2] = fR1.x + bhr1; acc[0][3] = fR1.y + bhr1;
        acc[1][0] = fZ0.x + bhz0; acc[1][1] = fZ0.y + bhz0;
        acc[1][2] = fZ1.x + bhz1; acc[1][3] = fZ1.y + bhz1;
        acc[2][0] = bhn0; acc[2][1] = bhn0;
        acc[2][2] = bhn1; acc[2][3] = bhn1;
        float fxn[4] = {fN0.x, fN0.y, fN1.x, fN1.y};

        #pragma unroll
        for (int mt = 0; mt < 3; mt++) {
            #pragma unroll
            for (int kt = 0; kt < 4; kt++) {
                asm volatile(
                    "mma.sync.aligned.m16n8k16.row.col.f32.f16.f16.f32 "
                    "{%0,%1,%2,%3}, {%4,%5,%6,%7}, {%8,%9}, {%0,%1,%2,%3};\n"
                    : "+f"(acc[mt][0]), "+f"(acc[mt][1]), "+f"(acc[mt][2]), "+f"(acc[mt][3])
                    : "r"(Ahi[mt][kt][0]), "r"(Ahi[mt][kt][1]), "r"(Ahi[mt][kt][2]), "r"(Ahi[mt][kt][3]),
                      "r"(bhi[kt][0]), "r"(bhi[kt][1]));
                asm volatile(
                    "mma.sync.aligned.m16n8k16.row.col.f32.f16.f16.f32 "
                    "{%0,%1,%2,%3}, {%4,%5,%6,%7}, {%8,%9}, {%0,%1,%2,%3};\n"
                    : "+f"(acc[mt][0]), "+f"(acc[mt][1]), "+f"(acc[mt][2]), "+f"(acc[mt][3])
                    : "r"(Ahi[mt][kt][0]), "r"(Ahi[mt][kt][1]), "r"(Ahi[mt][kt][2]), "r"(Ahi[mt][kt][3]),
                      "r"(blo[kt][0]), "r"(blo[kt][1]));
                asm volatile(
                    "mma.sync.aligned.m16n8k16.row.col.f32.f16.f16.f32 "
                    "{%0,%1,%2,%3}, {%4,%5,%6,%7}, {%8,%9}, {%0,%1,%2,%3};\n"
                    : "+f"(acc[mt][0]), "+f"(acc[mt][1]), "+f"(acc[mt][2]), "+f"(acc[mt][3])
                    : "r"(Alo[mt][kt][0]), "r"(Alo[mt][kt][1]), "r"(Alo[mt][kt][2]), "r"(Alo[mt][kt][3]),
                      "r"(bhi[kt][0]), "r"(bhi[kt][1]));
            }
        }

        // gates (registers only)
        #pragma unroll
        for (int e = 0; e < 4; e++) {
            float rr = sigf(acc[0][e]);
            float zz = sigf(acc[1][e]);
            float nn = tanhf_fast(fxn[e] + rr * acc[2][e]);
            float hn = (1.f - zz) * nn + zz * hp[e];
            int sq = (e & 1) ? seq1 : seq0;
            hp[e] = (t < sq) ? hn : hp[e];
        }

        // store h_new (fp16 hi/lo) to other buffer
        const int b2 = buf ^ 1;
        #pragma unroll
        for (int e = 0; e < 4; e++) {
            const int nn_ = n0 + (e & 1);
            const int jj_ = (e < 2) ? j0 : j1;
            __half hi = __float2half(hp[e]);
            __half lo = __float2half(hp[e] - __half2float(hi));
            SH(b2, 0, nn_, jj_) = hi;
            SH(b2, 1, nn_, jj_) = lo;
        }

        cR0 = pR0; cR1 = pR1; cZ0 = pZ0; cZ1 = pZ1; cN0 = pN0; cN1 = pN1;
        __syncthreads();
    }

    // write final h
    g_h[(size_t)(row0 + n0)     * HH + j0] = hp[0];
    g_h[(size_t)(row0 + n0 + 1) * HH + j0] = hp[1];
    g_h[(size_t)(row0 + n0)     * HH + j1] = hp[2];
    g_h[(size_t)(row0 + n0 + 1) * HH + j1] = hp[3];
#undef SH
}

// =====================================================================
// z0: one warp per row (8 warps/CTA, 256 CTAs)
// =====================================================================
__global__ void __launch_bounds__(256) z0_kernel(
    const float* __restrict__ Wz0, const float* __restrict__ bz0,
    const float* __restrict__ eps)
{
    __shared__ float sH[8][64];
    const int w = threadIdx.x >> 5, l = threadIdx.x & 31;
    const int row = blockIdx.x * 8 + w;
    sH[w][l]      = g_h[(size_t)row * HH + l];
    sH[w][l + 32] = g_h[(size_t)row * HH + l + 32];
    __syncwarp();
    float m = bz0[l], lv = bz0[l + 32];
    #pragma unroll 8
    for (int f = 0; f < HH; f++) {
        float hf = sH[w][f];
        m  = fmaf(__ldg(Wz0 + l * HH + f), hf, m);
        lv = fmaf(__ldg(Wz0 + (l + 32) * HH + f), hf, lv);
    }
    g_z0[(size_t)row * LL + l] = m + eps[(size_t)row * LL + l] * __expf(0.5f * lv);
    float kterm = 1.f + lv - m * m - __expf(lv);
    #pragma unroll
    for (int off = 16; off; off >>= 1) kterm += __shfl_down_sync(0xffffffffu, kterm, off);
    if (l == 0) g_klrow[row] = kterm;
}

// =====================================================================
// ODE: fixed-step RK4, NSTEP steps over [0,48]. 128 CTAs x 256 thr.
// =====================================================================
#define NSTEP 8
#define ODE_SMEM_F (2048 + 4096 + 2048 + 64 + 64 + 32 + 512 + 512 + 512 + 512 + 1024 + 1024)
#define ODE_SMEM_B (ODE_SMEM_F * 4)

__device__ __forceinline__ void ode_eval(
    const float* __restrict__ zin, float* __restrict__ kb,
    const float* sW1, const float* sW2, const float* sW3,
    const float* sb1, const float* sb2, const float* sb3,
    float* sh1, float* sh2, int tid)
{
    {
        const int o0 = (tid & 31) * 2, r0 = (tid >> 5) * 2;
        float a00 = sb1[o0], a01 = a00, a10 = sb1[o0 + 1], a11 = a10;
        #pragma unroll 8
        for (int f = 0; f < LL; f++) {
            float2 w  = *(const float2*)(sW1 + f * 64 + o0);
            float2 zv = *(const float2*)(zin + f * 16 + r0);
            a00 = fmaf(w.x, zv.x, a00); a01 = fmaf(w.x, zv.y, a01);
            a10 = fmaf(w.y, zv.x, a10); a11 = fmaf(w.y, zv.y, a11);
        }
        sh1[o0 * 16 + r0]           = tanhf_fast(a00);
        sh1[o0 * 16 + r0 + 1]       = tanhf_fast(a01);
        sh1[(o0 + 1) * 16 + r0]     = tanhf_fast(a10);
        sh1[(o0 + 1) * 16 + r0 + 1] = tanhf_fast(a11);
    }
    __syncthreads();
    {
        const int o0 = (tid & 31) * 2, r0 = (tid >> 5) * 2;
        float a00 = sb2[o0], a01 = a00, a10 = sb2[o0 + 1], a11 = a10;
        #pragma unroll 8
        for (int f = 0; f < OHH; f++) {
            float2 w  = *(const float2*)(sW2 + f * 64 + o0);
            float2 zv = *(const float2*)(sh1 + f * 16 + r0);
            a00 = fmaf(w.x, zv.x, a00); a01 = fmaf(w.x, zv.y, a01);
            a10 = fmaf(w.y, zv.x, a10); a11 = fmaf(w.y, zv.y, a11);
        }
        sh2[o0 * 16 + r0]           = tanhf_fast(a00);
        sh2[o0 * 16 + r0 + 1]       = tanhf_fast(a01);
        sh2[(o0 + 1) * 16 + r0]     = tanhf_fast(a10);
        sh2[(o0 + 1) * 16 + r0 + 1] = tanhf_fast(a11);
    }
    __syncthreads();
    {
        const int o0 = (tid & 15) * 2, r = tid >> 4;
        float a0 = sb3[o0], a1 = sb3[o0 + 1];
        #pragma unroll 8
        for (int f = 0; f < OHH; f++) {
            float2 w = *(const float2*)(sW3 + f * 32 + o0);
            float hv = sh2[f * 16 + r];
            a0 = fmaf(w.x, hv, a0);
            a1 = fmaf(w.y, hv, a1);
        }
        kb[o0 * 16 + r]       = a0;
        kb[(o0 + 1) * 16 + r] = a1;
    }
    __syncthreads();
}

__global__ void __launch_bounds__(256, 1) ode_kernel(
    const float* __restrict__ W1, const float* __restrict__ b1,
    const float* __restrict__ W2, const float* __restrict__ b2,
    const float* __restrict__ W3, const float* __restrict__ b3)
{
    extern __shared__ float sm[];
    float* sW1 = sm;
    float* sW2 = sW1 + 2048;
    float* sW3 = sW2 + 4096;
    float* sb1 = sW3 + 2048;
    float* sb2 = sb1 + 64;
    float* sb3 = sb2 + 64;
    float* zc  = sb3 + 32;
    float* za  = zc + 512;
    float* zin = za + 512;
    float* kb  = zin + 512;
    float* sh1 = kb + 512;
    float* sh2 = sh1 + 1024;

    const int tid = threadIdx.x;
    const int row0 = blockIdx.x * 16;

    for (int i = tid; i < OHH * LL; i += 256) {
        int o = i >> 5, f = i & 31;
        sW1[f * 64 + o] = W1[i];
        sW3[o * 32 + f] = W3[f * 64 + o];
    }
    for (int i = tid; i < OHH * OHH; i += 256) {
        int o = i >> 6, f = i & 63;
        sW2[f * 64 + o] = W2[i];
    }
    if (tid < 64) { sb1[tid] = b1[tid]; sb2[tid] = b2[tid]; }
    if (tid < 32) sb3[tid] = b3[tid];
    #pragma unroll
    for (int k = 0; k < 2; k++) {
        int idx = tid + k * 256;
        int l2 = idx >> 4, rr = idx & 15;
        zc[l2 * 16 + rr] = g_z0[(size_t)(row0 + rr) * LL + l2];
    }
    __syncthreads();

    const float hs = 48.0f / NSTEP;
    for (int s = 0; s < NSTEP; s++) {
        ode_eval(zc, kb, sW1, sW2, sW3, sb1, sb2, sb3, sh1, sh2, tid);
        #pragma unroll
        for (int k = 0; k < 2; k++) {
            int i = tid + k * 256;
            za[i]  = fmaf(hs / 6.f, kb[i], zc[i]);
            zin[i] = fmaf(hs * 0.5f, kb[i], zc[i]);
        }
        __syncthreads();
        ode_eval(zin, kb, sW1, sW2, sW3, sb1, sb2, sb3, sh1, sh2, tid);
        #pragma unroll
        for (int k = 0; k < 2; k++) {
            int i = tid + k * 256;
            za[i]  = fmaf(hs / 3.f, kb[i], za[i]);
            zin[i] = fmaf(hs * 0.5f, kb[i], zc[i]);
        }
        __syncthreads();
        ode_eval(zin, kb, sW1, sW2, sW3, sb1, sb2, sb3, sh1, sh2, tid);
        #pragma unroll
        for (int k = 0; k < 2; k++) {
            int i = tid + k * 256;
            za[i]  = fmaf(hs / 3.f, kb[i], za[i]);
            zin[i] = fmaf(hs, kb[i], zc[i]);
        }
        __syncthreads();
        ode_eval(zin, kb, sW1, sW2, sW3, sb1, sb2, sb3, sh1, sh2, tid);
        #pragma unroll
        for (int k = 0; k < 2; k++) {
            int i = tid + k * 256;
            zc[i] = fmaf(hs / 6.f, kb[i], za[i]);
        }
        __syncthreads();
    }

    #pragma unroll
    for (int k = 0; k < 2; k++) {
        int idx = tid + k * 256;
        int l2 = idx >> 4, rr = idx & 15;
        g_zf[(size_t)(row0 + rr) * LL + l2] = zc[l2 * 16 + rr];
    }
}

// =====================================================================
// Decoder: one warp per row
// =====================================================================
__global__ void __launch_bounds__(256) dec_kernel(
    const float* __restrict__ W1, const float* __restrict__ b1,
    const float* __restrict__ W2, const float* __restrict__ b2,
    float* __restrict__ out)
{
    __shared__ float sz[8][32];
    const int w = threadIdx.x >> 5, l = threadIdx.x & 31;
    const int row = blockIdx.x * 8 + w;
    sz[w][l] = g_zf[(size_t)row * LL + l];
    __syncwarp();
    float a0 = b1[l], a1 = b1[l + 32];
    #pragma unroll 8
    for (int f = 0; f < LL; f++) {
        float zv = sz[w][f];
        a0 = fmaf(__ldg(W1 + l * LL + f), zv, a0);
        a1 = fmaf(__ldg(W1 + (l + 32) * LL + f), zv, a1);
    }
    a0 = fmaxf(a0, 0.f); a1 = fmaxf(a1, 0.f);
    float p = a0 * __ldg(W2 + l) + a1 * __ldg(W2 + l + 32);
    #pragma unroll
    for (int off = 16; off; off >>= 1) p += __shfl_down_sync(0xffffffffu, p, off);
    if (l == 0) out[row] = p + b2[0];
}

__global__ void __launch_bounds__(1024) kl_kernel(float* __restrict__ out)
{
    __shared__ float s[1024];
    const int t = threadIdx.x;
    s[t] = g_klrow[t] + g_klrow[t + 1024];
    __syncthreads();
    for (int o = 512; o; o >>= 1) {
        if (t < o) s[t] += s[t + o];
        __syncthreads();
    }
    if (t == 0) out[BB] = -0.5f * s[0] / ((float)BB * (float)LL);
}

// =====================================================================
extern "C" void kernel_launch(void* const* d_in, const int* in_sizes, int n_in,
                              void* d_out, int out_size)
{
    const float* values = (const float*)d_in[1];
    const float* maskp  = (const float*)d_in[2];
    const int*   seql   = (const int*)d_in[3];
    const float* eps    = (const float*)d_in[4];
    const float* W_ih   = (const float*)d_in[5];
    const float* W_hh   = (const float*)d_in[6];
    const float* b_ih   = (const float*)d_in[7];
    const float* b_hh   = (const float*)d_in[8];
    const float* W_z0   = (const float*)d_in[9];
    const float* b_z0   = (const float*)d_in[10];
    const float* oW1    = (const float*)d_in[11];
    const float* ob1    = (const float*)d_in[12];
    const float* oW2    = (const float*)d_in[13];
    const float* ob2    = (const float*)d_in[14];
    const float* oW3    = (const float*)d_in[15];
    const float* ob3    = (const float*)d_in[16];
    const float* dW1    = (const float*)d_in[17];
    const float* db1    = (const float*)d_in[18];
    const float* dW2    = (const float*)d_in[19];
    const float* db2    = (const float*)d_in[20];
    float* out = (float*)d_out;

    cudaFuncSetAttribute(gru_kernel, cudaFuncAttributeMaxDynamicSharedMemorySize, GRU_SMEM_B);
    cudaFuncSetAttribute(ode_kernel, cudaFuncAttributeMaxDynamicSharedMemorySize, ODE_SMEM_B);

    xp_kernel<<<dim3(16, 256), 256>>>(values, maskp, W_ih, b_ih);
    gru_kernel<<<128, 256, GRU_SMEM_B>>>(seql, W_hh, b_hh);
    z0_kernel<<<256, 256>>>(W_z0, b_z0, eps);
    ode_kernel<<<128, 256, ODE_SMEM_B>>>(oW1, ob1, oW2, ob2, oW3, ob3);
    dec_kernel<<<256, 256>>>(dW1, db1, dW2, db2, out);
    kl_kernel<<<1, 1024>>>(out);
}

// round 8
// speedup vs baseline: 2.5660x; 1.0225x over previous
#include <cuda_runtime.h>
#include <cuda_fp16.h>
#include <cstdint>

#define BB 2048
#define TT 256
#define NVV 32
#define HH 64
#define GG 192
#define LL 32
#define OHH 64

__device__ float g_h[BB * HH];
__device__ float g_klrow[BB];
// xp[t][g][b] fp16, t = scan step (time-reversed). 201 MB scratch.
__device__ __half g_xph[(size_t)TT * GG * BB];

__device__ __forceinline__ float tanh_hw(float x) {
    float y;
    asm("tanh.approx.f32 %0, %1;" : "=f"(y) : "f"(x));
    return y;
}
__device__ __forceinline__ float sig_hw(float x) {
    return fmaf(tanh_hw(0.5f * x), 0.5f, 0.5f);
}

// =====================================================================
// xp GEMM via fp16 tensor cores, fp32 accumulate. (unchanged)
// =====================================================================
__global__ void __launch_bounds__(256) xp_kernel(
    const float* __restrict__ values, const float* __restrict__ maskp,
    const float* __restrict__ W_ih, const float* __restrict__ b_ih)
{
    __shared__ __half sW[192 * 72];
    __shared__ __half sX[128 * 72];

    const int tid = threadIdx.x;
    const int bb = blockIdx.x;
    const int t = blockIdx.y;
    const int tt = TT - 1 - t;
    const int bbase = bb * 128;

    for (int i = tid; i < GG * HH; i += 256) {
        int g = i >> 6, f = i & 63;
        sW[g * 72 + f] = __float2half(W_ih[i]);
    }
    for (int i = tid; i < 128 * HH; i += 256) {
        int bl = i >> 6, f = i & 63;
        size_t base = (size_t)(bbase + bl) * TT * NVV + (size_t)tt * NVV;
        float v = (f < NVV) ? values[base + f] : maskp[base + f - NVV];
        sX[bl * 72 + f] = __float2half(v);
    }
    __syncthreads();

    const int w = tid >> 5, l = tid & 31;
    const int wg = w >> 2;
    const int wb = w & 3;
    const int l4 = l >> 2;
    const int l2 = (l & 3) * 2;

    #pragma unroll
    for (int gt = 0; gt < 6; gt++) {
        const int g0 = wg * 96 + gt * 16;
        uint32_t a[4][4];
        #pragma unroll
        for (int kk = 0; kk < 4; kk++) {
            const __half* p = &sW[(g0 + l4) * 72 + kk * 16 + l2];
            a[kk][0] = *(const uint32_t*)(p);
            a[kk][1] = *(const uint32_t*)(p + 8 * 72);
            a[kk][2] = *(const uint32_t*)(p + 8);
            a[kk][3] = *(const uint32_t*)(p + 8 * 72 + 8);
        }
        const float bias0 = __ldg(b_ih + g0 + l4);
        const float bias1 = __ldg(b_ih + g0 + 8 + l4);

        #pragma unroll
        for (int bt = 0; bt < 4; bt++) {
            const int b0 = wb * 32 + bt * 8;
            float c0 = bias0, c1 = bias0, c2 = bias1, c3 = bias1;
            #pragma unroll
            for (int kk = 0; kk < 4; kk++) {
                const __half* bp = &sX[(b0 + l4) * 72 + kk * 16 + l2];
                uint32_t br0 = *(const uint32_t*)(bp);
                uint32_t br1 = *(const uint32_t*)(bp + 8);
                asm volatile(
                    "mma.sync.aligned.m16n8k16.row.col.f32.f16.f16.f32 "
                    "{%0,%1,%2,%3}, {%4,%5,%6,%7}, {%8,%9}, {%0,%1,%2,%3};\n"
                    : "+f"(c0), "+f"(c1), "+f"(c2), "+f"(c3)
                    : "r"(a[kk][0]), "r"(a[kk][1]), "r"(a[kk][2]), "r"(a[kk][3]),
                      "r"(br0), "r"(br1));
            }
            const int gg = g0 + l4;
            const int bglob = bbase + b0 + l2;
            size_t base = ((size_t)t * GG + gg) * BB + bglob;
            *(__half2*)(g_xph + base) = __floats2half2_rn(c0, c1);
            *(__half2*)(g_xph + base + (size_t)8 * BB) = __floats2half2_rn(c2, c3);
        }
    }
}

// =====================================================================
// GRU scan with split-fp16 tensor-core h-matvec. (R6 structure,
// activations switched to HW tanh)
// =====================================================================
#define GRU_SMEM_B (192*72*2*2 + 2*2*16*72*2)

__global__ void __launch_bounds__(256, 1) gru_kernel(
    const int* __restrict__ seqlen,
    const float* __restrict__ W_hh, const float* __restrict__ b_hh)
{
    extern __shared__ char smem[];
    __half* sWhi = (__half*)smem;            // [192][72]
    __half* sWlo = sWhi + 192 * 72;
    __half* sH   = sWlo + 192 * 72;          // [2][2][16][72]
#define SH(buf, sp, n, k) sH[((((buf) * 2 + (sp)) * 16) + (n)) * 72 + (k)]

    const int tid  = threadIdx.x;
    const int row0 = blockIdx.x * 16;

    for (int i = tid; i < GG * HH; i += 256) {
        int g = i >> 6, k = i & 63;
        float wv = W_hh[i];
        __half hi = __float2half(wv);
        __half lo = __float2half(wv - __half2float(hi));
        sWhi[g * 72 + k] = hi;
        sWlo[g * 72 + k] = lo;
    }
    for (int i = tid; i < 2 * 2 * 16 * 72; i += 256) sH[i] = __float2half(0.f);
    __syncthreads();

    const int l  = tid & 31;
    const int w  = tid >> 5;
    const int mw = w & 3;
    const int nt = w >> 2;
    const int r  = l >> 2;
    const int cq = (l & 3) * 2;

    uint32_t Ahi[3][4][4], Alo[3][4][4];
    #pragma unroll
    for (int mt = 0; mt < 3; mt++) {
        const int g0 = 16 * mw + 64 * mt;
        #pragma unroll
        for (int kt = 0; kt < 4; kt++) {
            const int k0 = kt * 16 + cq;
            Ahi[mt][kt][0] = *(const uint32_t*)&sWhi[(g0 + r) * 72 + k0];
            Ahi[mt][kt][1] = *(const uint32_t*)&sWhi[(g0 + r + 8) * 72 + k0];
            Ahi[mt][kt][2] = *(const uint32_t*)&sWhi[(g0 + r) * 72 + k0 + 8];
            Ahi[mt][kt][3] = *(const uint32_t*)&sWhi[(g0 + r + 8) * 72 + k0 + 8];
            Alo[mt][kt][0] = *(const uint32_t*)&sWlo[(g0 + r) * 72 + k0];
            Alo[mt][kt][1] = *(const uint32_t*)&sWlo[(g0 + r + 8) * 72 + k0];
            Alo[mt][kt][2] = *(const uint32_t*)&sWlo[(g0 + r) * 72 + k0 + 8];
            Alo[mt][kt][3] = *(const uint32_t*)&sWlo[(g0 + r + 8) * 72 + k0 + 8];
        }
    }

    const int j0 = 16 * mw + r;
    const int j1 = j0 + 8;
    const int n0 = 8 * nt + cq;
    const float bhr0 = __ldg(b_hh + j0),        bhr1 = __ldg(b_hh + j1);
    const float bhz0 = __ldg(b_hh + 64 + j0),   bhz1 = __ldg(b_hh + 64 + j1);
    const float bhn0 = __ldg(b_hh + 128 + j0),  bhn1 = __ldg(b_hh + 128 + j1);
    const int seq0 = __ldg(seqlen + row0 + n0);
    const int seq1 = __ldg(seqlen + row0 + n0 + 1);

    float hp[4] = {0.f, 0.f, 0.f, 0.f};

    const size_t xo = (size_t)row0 + n0;
    __half2 cR0 = *(const __half2*)&g_xph[(size_t)(j0)       * BB + xo];
    __half2 cR1 = *(const __half2*)&g_xph[(size_t)(j1)       * BB + xo];
    __half2 cZ0 = *(const __half2*)&g_xph[(size_t)(j0 + 64)  * BB + xo];
    __half2 cZ1 = *(const __half2*)&g_xph[(size_t)(j1 + 64)  * BB + xo];
    __half2 cN0 = *(const __half2*)&g_xph[(size_t)(j0 + 128) * BB + xo];
    __half2 cN1 = *(const __half2*)&g_xph[(size_t)(j1 + 128) * BB + xo];
    __syncthreads();

    for (int t = 0; t < TT; t++) {
        const int buf = t & 1;
        __half2 pR0, pR1, pZ0, pZ1, pN0, pN1;
        if (t + 1 < TT) {
            const __half* nb = g_xph + (size_t)(t + 1) * GG * BB + xo;
            pR0 = *(const __half2*)&nb[(size_t)(j0)       * BB];
            pR1 = *(const __half2*)&nb[(size_t)(j1)       * BB];
            pZ0 = *(const __half2*)&nb[(size_t)(j0 + 64)  * BB];
            pZ1 = *(const __half2*)&nb[(size_t)(j1 + 64)  * BB];
            pN0 = *(const __half2*)&nb[(size_t)(j0 + 128) * BB];
            pN1 = *(const __half2*)&nb[(size_t)(j1 + 128) * BB];
        }

        uint32_t bhi[4][2], blo[4][2];
        const int bn = 8 * nt + r;
        #pragma unroll
        for (int kt = 0; kt < 4; kt++) {
            const int k0 = kt * 16 + cq;
            bhi[kt][0] = *(const uint32_t*)&SH(buf, 0, bn, k0);
            bhi[kt][1] = *(const uint32_t*)&SH(buf, 0, bn, k0 + 8);
            blo[kt][0] = *(const uint32_t*)&SH(buf, 1, bn, k0);
            blo[kt][1] = *(const uint32_t*)&SH(buf, 1, bn, k0 + 8);
        }

        float2 fR0 = __half22float2(cR0), fR1 = __half22float2(cR1);
        float2 fZ0 = __half22float2(cZ0), fZ1 = __half22float2(cZ1);
        float2 fN0 = __half22float2(cN0), fN1 = __half22float2(cN1);
        float acc[3][4];
        acc[0][0] = fR0.x + bhr0; acc[0][1] = fR0.y + bhr0;
        acc[0][2] = fR1.x + bhr1; acc[0][3] = fR1.y + bhr1;
        acc[1][0] = fZ0.x + bhz0; acc[1][1] = fZ0.y + bhz0;
        acc[1][2] = fZ1.x + bhz1; acc[1][3] = fZ1.y + bhz1;
        acc[2][0] = bhn0; acc[2][1] = bhn0;
        acc[2][2] = bhn1; acc[2][3] = bhn1;
        float fxn[4] = {fN0.x, fN0.y, fN1.x, fN1.y};

        #pragma unroll
        for (int mt = 0; mt < 3; mt++) {
            #pragma unroll
            for (int kt = 0; kt < 4; kt++) {
                asm volatile(
                    "mma.sync.aligned.m16n8k16.row.col.f32.f16.f16.f32 "
                    "{%0,%1,%2,%3}, {%4,%5,%6,%7}, {%8,%9}, {%0,%1,%2,%3};\n"
                    : "+f"(acc[mt][0]), "+f"(acc[mt][1]), "+f"(acc[mt][2]), "+f"(acc[mt][3])
                    : "r"(Ahi[mt][kt][0]), "r"(Ahi[mt][kt][1]), "r"(Ahi[mt][kt][2]), "r"(Ahi[mt][kt][3]),
                      "r"(bhi[kt][0]), "r"(bhi[kt][1]));
                asm volatile(
                    "mma.sync.aligned.m16n8k16.row.col.f32.f16.f16.f32 "
                    "{%0,%1,%2,%3}, {%4,%5,%6,%7}, {%8,%9}, {%0,%1,%2,%3};\n"
                    : "+f"(acc[mt][0]), "+f"(acc[mt][1]), "+f"(acc[mt][2]), "+f"(acc[mt][3])
                    : "r"(Ahi[mt][kt][0]), "r"(Ahi[mt][kt][1]), "r"(Ahi[mt][kt][2]), "r"(Ahi[mt][kt][3]),
                      "r"(blo[kt][0]), "r"(blo[kt][1]));
                asm volatile(
                    "mma.sync.aligned.m16n8k16.row.col.f32.f16.f16.f32 "
                    "{%0,%1,%2,%3}, {%4,%5,%6,%7}, {%8,%9}, {%0,%1,%2,%3};\n"
                    : "+f"(acc[mt][0]), "+f"(acc[mt][1]), "+f"(acc[mt][2]), "+f"(acc[mt][3])
                    : "r"(Alo[mt][kt][0]), "r"(Alo[mt][kt][1]), "r"(Alo[mt][kt][2]), "r"(Alo[mt][kt][3]),
                      "r"(bhi[kt][0]), "r"(bhi[kt][1]));
            }
        }

        #pragma unroll
        for (int e = 0; e < 4; e++) {
            float rr = sig_hw(acc[0][e]);
            float zz = sig_hw(acc[1][e]);
            float nn = tanh_hw(fxn[e] + rr * acc[2][e]);
            float hn = (1.f - zz) * nn + zz * hp[e];
            int sq = (e & 1) ? seq1 : seq0;
            hp[e] = (t < sq) ? hn : hp[e];
        }

        const int b2 = buf ^ 1;
        #pragma unroll
        for (int e = 0; e < 4; e++) {
            const int nn_ = n0 + (e & 1);
            const int jj_ = (e < 2) ? j0 : j1;
            __half hi = __float2half(hp[e]);
            __half lo = __float2half(hp[e] - __half2float(hi));
            SH(b2, 0, nn_, jj_) = hi;
            SH(b2, 1, nn_, jj_) = lo;
        }

        cR0 = pR0; cR1 = pR1; cZ0 = pZ0; cZ1 = pZ1; cN0 = pN0; cN1 = pN1;
        __syncthreads();
    }

    g_h[(size_t)(row0 + n0)     * HH + j0] = hp[0];
    g_h[(size_t)(row0 + n0 + 1) * HH + j0] = hp[1];
    g_h[(size_t)(row0 + n0)     * HH + j1] = hp[2];
    g_h[(size_t)(row0 + n0 + 1) * HH + j1] = hp[3];
#undef SH
}

// =====================================================================
// Fused tail: z0 -> RK4 ODE -> decoder -> KL partials.
// grid 512 CTAs x 128 thr, 4 rows/CTA. ~39 KB static SMEM -> 3-4 CTA/SM.
// State layouts: zc/za/zin/kb = [l][4rows]; sh1/sh2 = [o][4rows].
// =====================================================================
#define NSTEP 8
#define R4 4

__global__ void __launch_bounds__(128) tail_kernel(
    const float* __restrict__ eps,
    const float* __restrict__ Wz0, const float* __restrict__ bz0,
    const float* __restrict__ W1, const float* __restrict__ b1,
    const float* __restrict__ W2, const float* __restrict__ b2,
    const float* __restrict__ W3, const float* __restrict__ b3,
    const float* __restrict__ dW1, const float* __restrict__ db1,
    const float* __restrict__ dW2, const float* __restrict__ db2,
    float* __restrict__ out)
{
    __shared__ float sW1[32 * 64];   // [f][o]
    __shared__ float sW2[64 * 64];   // [f][o]
    __shared__ float sW3[64 * 32];   // [f2][l]
    __shared__ float sb1[64], sb2[64], sb3[32];
    __shared__ float sH[R4 * 64];    // [row][f]
    __shared__ float z0p[R4 * 64];   // [row][o]
    __shared__ float zc[32 * R4], za[32 * R4], zin[32 * R4], kb[32 * R4];
    __shared__ float sh1[64 * R4], sh2[64 * R4];

    const int tid = threadIdx.x;
    const int row0 = blockIdx.x * R4;

    for (int i = tid; i < OHH * LL; i += 128) {
        int o = i >> 5, f = i & 31;
        sW1[f * 64 + o] = W1[i];                 // W1 (64,32)
    }
    for (int i = tid; i < LL * OHH; i += 128) {
        int l = i >> 6, f2 = i & 63;
        sW3[f2 * 32 + l] = W3[i];                // W3 (32,64)
    }
    for (int i = tid; i < OHH * OHH; i += 128) {
        int o = i >> 6, f = i & 63;
        sW2[f * 64 + o] = W2[i];                 // W2 (64,64)
    }
    if (tid < 64) { sb1[tid] = b1[tid]; sb2[tid] = b2[tid]; }
    if (tid < 32) sb3[tid] = b3[tid];
    for (int i = tid; i < R4 * 64; i += 128)
        sH[i] = g_h[(size_t)(row0 + (i >> 6)) * HH + (i & 63)];
    __syncthreads();

    // ---- z0 projection: z0p[row][o] = bz0[o] + Wz0[o]·h[row]
    {
        const int o = tid & 63, rp = tid >> 6;   // rows rp, rp+2
        float m0 = __ldg(bz0 + o), m1 = m0;
        #pragma unroll 8
        for (int f = 0; f < HH; f++) {
            float wv = __ldg(Wz0 + o * HH + f);
            m0 = fmaf(wv, sH[rp * 64 + f], m0);
            m1 = fmaf(wv, sH[(rp + 2) * 64 + f], m1);
        }
        z0p[rp * 64 + o] = m0;
        z0p[(rp + 2) * 64 + o] = m1;
    }
    __syncthreads();

    // ---- reparameterize + KL partial. warp w = row.
    {
        const int row = tid >> 5, l = tid & 31;
        float m  = z0p[row * 64 + l];
        float lv = z0p[row * 64 + 32 + l];
        float z = m + eps[(size_t)(row0 + row) * LL + l] * __expf(0.5f * lv);
        zc[l * R4 + row] = z;
        float kt = 1.f + lv - m * m - __expf(lv);
        #pragma unroll
        for (int off = 16; off; off >>= 1) kt += __shfl_down_sync(0xffffffffu, kt, off);
        if (l == 0) g_klrow[row0 + row] = kt;
    }
    __syncthreads();

    // ---- RK4
    const float hs = 48.0f / NSTEP;
    const int o64 = tid & 63, rp = tid >> 6;     // layer1/2 tile
    const int o32 = tid & 31, rw = tid >> 5;     // layer3 tile

#define ODE_EVAL(SRC)                                                        \
    {   /* layer1: 64 out x 32 in */                                         \
        float a0 = sb1[o64], a1 = a0;                                        \
        _Pragma("unroll 8")                                                  \
        for (int f = 0; f < LL; f++) {                                       \
            float wv = sW1[f * 64 + o64];                                    \
            float4 zv = *(const float4*)((SRC) + f * R4);                    \
            float u0 = rp ? zv.y : zv.x;                                     \
            float u1 = rp ? zv.w : zv.z;                                     \
            a0 = fmaf(wv, u0, a0); a1 = fmaf(wv, u1, a1);                    \
        }                                                                    \
        sh1[o64 * R4 + rp]     = tanh_hw(a0);                                \
        sh1[o64 * R4 + rp + 2] = tanh_hw(a1);                                \
    }                                                                        \
    __syncthreads();                                                         \
    {   /* layer2: 64 out x 64 in */                                         \
        float a0 = sb2[o64], a1 = a0;                                        \
        _Pragma("unroll 8")                                                  \
        for (int f = 0; f < OHH; f++) {                                      \
            float wv = sW2[f * 64 + o64];                                    \
            float4 zv = *(const float4*)(sh1 + f * R4);                      \
            float u0 = rp ? zv.y : zv.x;                                     \
            float u1 = rp ? zv.w : zv.z;                                     \
            a0 = fmaf(wv, u0, a0); a1 = fmaf(wv, u1, a1);                    \
        }                                                                    \
        sh2[o64 * R4 + rp]     = tanh_hw(a0);                                \
        sh2[o64 * R4 + rp + 2] = tanh_hw(a1);                                \
    }                                                                        \
    __syncthreads();                                                         \
    {   /* layer3: 32 out x 64 in */                                         \
        float a = sb3[o32];                                                  \
        _Pragma("unroll 8")                                                  \
        for (int f = 0; f < OHH; f++)                                        \
            a = fmaf(sW3[f * 32 + o32], sh2[f * R4 + rw], a);                \
        kb[o32 * R4 + rw] = a;                                               \
    }                                                                        \
    __syncthreads();

    for (int s = 0; s < NSTEP; s++) {
        ODE_EVAL(zc)
        za[tid]  = fmaf(hs / 6.f, kb[tid], zc[tid]);
        zin[tid] = fmaf(hs * 0.5f, kb[tid], zc[tid]);
        __syncthreads();
        ODE_EVAL(zin)
        za[tid]  = fmaf(hs / 3.f, kb[tid], za[tid]);
        zin[tid] = fmaf(hs * 0.5f, kb[tid], zc[tid]);
        __syncthreads();
        ODE_EVAL(zin)
        za[tid]  = fmaf(hs / 3.f, kb[tid], za[tid]);
        zin[tid] = fmaf(hs, kb[tid], zc[tid]);
        __syncthreads();
        ODE_EVAL(zin)
        zc[tid] = fmaf(hs / 6.f, kb[tid], za[tid]);
        __syncthreads();
    }
#undef ODE_EVAL

    // ---- decoder: hidden = relu(zf @ dW1.T + db1); logit = hidden @ dW2.T + db2
    {
        float a0 = __ldg(db1 + o64), a1 = a0;
        #pragma unroll 8
        for (int f = 0; f < LL; f++) {
            float wv = __ldg(dW1 + o64 * LL + f);
            float4 zv = *(const float4*)(zc + f * R4);
            float u0 = rp ? zv.y : zv.x;
            float u1 = rp ? zv.w : zv.z;
            a0 = fmaf(wv, u0, a0); a1 = fmaf(wv, u1, a1);
        }
        float w2 = __ldg(dW2 + o64);
        sh1[o64 * R4 + rp]     = fmaxf(a0, 0.f) * w2;
        sh1[o64 * R4 + rp + 2] = fmaxf(a1, 0.f) * w2;
    }
    __syncthreads();
    {
        const int row = tid >> 5, l = tid & 31;
        float s = sh1[l * R4 + row] + sh1[(l + 32) * R4 + row];
        #pragma unroll
        for (int off = 16; off; off >>= 1) s += __shfl_down_sync(0xffffffffu, s, off);
        if (l == 0) out[row0 + row] = s + __ldg(db2);
    }
}

__global__ void __launch_bounds__(1024) kl_kernel(float* __restrict__ out)
{
    __shared__ float s[1024];
    const int t = threadIdx.x;
    s[t] = g_klrow[t] + g_klrow[t + 1024];
    __syncthreads();
    for (int o = 512; o; o >>= 1) {
        if (t < o) s[t] += s[t + o];
        __syncthreads();
    }
    if (t == 0) out[BB] = -0.5f * s[0] / ((float)BB * (float)LL);
}

// =====================================================================
extern "C" void kernel_launch(void* const* d_in, const int* in_sizes, int n_in,
                              void* d_out, int out_size)
{
    const float* values = (const float*)d_in[1];
    const float* maskp  = (const float*)d_in[2];
    const int*   seql   = (const int*)d_in[3];
    const float* eps    = (const float*)d_in[4];
    const float* W_ih   = (const float*)d_in[5];
    const float* W_hh   = (const float*)d_in[6];
    const float* b_ih   = (const float*)d_in[7];
    const float* b_hh   = (const float*)d_in[8];
    const float* W_z0   = (const float*)d_in[9];
    const float* b_z0   = (const float*)d_in[10];
    const float* oW1    = (const float*)d_in[11];
    const float* ob1    = (const float*)d_in[12];
    const float* oW2    = (const float*)d_in[13];
    const float* ob2    = (const float*)d_in[14];
    const float* oW3    = (const float*)d_in[15];
    const float* ob3    = (const float*)d_in[16];
    const float* dW1    = (const float*)d_in[17];
    const float* db1    = (const float*)d_in[18];
    const float* dW2    = (const float*)d_in[19];
    const float* db2    = (const float*)d_in[20];
    float* out = (float*)d_out;

    cudaFuncSetAttribute(gru_kernel, cudaFuncAttributeMaxDynamicSharedMemorySize, GRU_SMEM_B);

    xp_kernel<<<dim3(16, 256), 256>>>(values, maskp, W_ih, b_ih);
    gru_kernel<<<128, 256, GRU_SMEM_B>>>(seql, W_hh, b_hh);
    tail_kernel<<<512, 128>>>(eps, W_z0, b_z0, oW1, ob1, oW2, ob2, oW3, ob3,
                              dW1, db1, dW2, db2, out);
    kl_kernel<<<1, 1024>>>(out);
}

// round 9
// speedup vs baseline: 2.8873x; 1.1252x over previous
#include <cuda_runtime.h>
#include <cuda_fp16.h>
#include <cstdint>

#define BB 2048
#define TT 256
#define NVV 32
#define HH 64
#define GG 192
#define LL 32
#define OHH 64

__device__ float g_h[BB * HH];
__device__ float g_klrow[BB];
// xp planes: [t][bpair(1024)][g(192)] as half2 (pair = 2 batch rows). 201 MB.
__device__ __half2 g_xp2[(size_t)TT * 1024 * GG];

__device__ __forceinline__ float tanh_hw(float x) {
    float y;
    asm("tanh.approx.f32 %0, %1;" : "=f"(y) : "f"(x));
    return y;
}
__device__ __forceinline__ float sig_hw(float x) {
    return fmaf(tanh_hw(0.5f * x), 0.5f, 0.5f);
}

// =====================================================================
// xp GEMM via fp16 tensor cores, fp32 accumulate.
// grid (16 b-blocks, 64 t-blocks) x 256 thr; 4 t per CTA (W staged once).
// Output layout: g_xp2[((t*1024)+bpair)*192 + g]
// =====================================================================
__global__ void __launch_bounds__(256) xp_kernel(
    const float* __restrict__ values, const float* __restrict__ maskp,
    const float* __restrict__ W_ih, const float* __restrict__ b_ih)
{
    __shared__ __half sW[192 * 72];
    __shared__ __half sX[128 * 72];

    const int tid = threadIdx.x;
    const int bbase = blockIdx.x * 128;

    for (int i = tid; i < GG * HH; i += 256) {
        int g = i >> 6, f = i & 63;
        sW[g * 72 + f] = __float2half(W_ih[i]);
    }

    const int w = tid >> 5, l = tid & 31;
    const int wg = w >> 2;
    const int wb = w & 3;
    const int l4 = l >> 2;
    const int l2 = (l & 3) * 2;

    for (int tloc = 0; tloc < 4; tloc++) {
        const int t = blockIdx.y * 4 + tloc;
        const int tt = TT - 1 - t;

        if (tloc > 0) __syncthreads();   // protect sX reuse
        for (int i = tid; i < 128 * HH; i += 256) {
            int bl = i >> 6, f = i & 63;
            size_t base = (size_t)(bbase + bl) * TT * NVV + (size_t)tt * NVV;
            float v = (f < NVV) ? values[base + f] : maskp[base + f - NVV];
            sX[bl * 72 + f] = __float2half(v);
        }
        __syncthreads();

        #pragma unroll
        for (int gt = 0; gt < 6; gt++) {
            const int g0 = wg * 96 + gt * 16;
            uint32_t a[4][4];
            #pragma unroll
            for (int kk = 0; kk < 4; kk++) {
                const __half* p = &sW[(g0 + l4) * 72 + kk * 16 + l2];
                a[kk][0] = *(const uint32_t*)(p);
                a[kk][1] = *(const uint32_t*)(p + 8 * 72);
                a[kk][2] = *(const uint32_t*)(p + 8);
                a[kk][3] = *(const uint32_t*)(p + 8 * 72 + 8);
            }
            const float bias0 = __ldg(b_ih + g0 + l4);
            const float bias1 = __ldg(b_ih + g0 + 8 + l4);

            #pragma unroll
            for (int bt = 0; bt < 4; bt++) {
                const int b0 = wb * 32 + bt * 8;
                float c0 = bias0, c1 = bias0, c2 = bias1, c3 = bias1;
                #pragma unroll
                for (int kk = 0; kk < 4; kk++) {
                    const __half* bp = &sX[(b0 + l4) * 72 + kk * 16 + l2];
                    uint32_t br0 = *(const uint32_t*)(bp);
                    uint32_t br1 = *(const uint32_t*)(bp + 8);
                    asm volatile(
                        "mma.sync.aligned.m16n8k16.row.col.f32.f16.f16.f32 "
                        "{%0,%1,%2,%3}, {%4,%5,%6,%7}, {%8,%9}, {%0,%1,%2,%3};\n"
                        : "+f"(c0), "+f"(c1), "+f"(c2), "+f"(c3)
                        : "r"(a[kk][0]), "r"(a[kk][1]), "r"(a[kk][2]), "r"(a[kk][3]),
                          "r"(br0), "r"(br1));
                }
                const int gg = g0 + l4;
                const int bpair = (bbase + b0 + l2) >> 1;
                size_t base = ((size_t)t * 1024 + bpair) * 192 + gg;
                g_xp2[base]     = __floats2half2_rn(c0, c1);
                g_xp2[base + 8] = __floats2half2_rn(c2, c3);
            }
        }
    }
}

// =====================================================================
// GRU scan with split-fp16 tensor-core h-matvec; coalesced xp planes +
// two-step-deep prefetch.
// =====================================================================
#define GRU_SMEM_B (192*72*2*2 + 2*2*16*72*2)

__global__ void __launch_bounds__(256, 1) gru_kernel(
    const int* __restrict__ seqlen,
    const float* __restrict__ W_hh, const float* __restrict__ b_hh)
{
    extern __shared__ char smem[];
    __half* sWhi = (__half*)smem;            // [192][72]
    __half* sWlo = sWhi + 192 * 72;
    __half* sH   = sWlo + 192 * 72;          // [2][2][16][72]
#define SH(buf, sp, n, k) sH[((((buf) * 2 + (sp)) * 16) + (n)) * 72 + (k)]

    const int tid  = threadIdx.x;
    const int row0 = blockIdx.x * 16;

    for (int i = tid; i < GG * HH; i += 256) {
        int g = i >> 6, k = i & 63;
        float wv = W_hh[i];
        __half hi = __float2half(wv);
        __half lo = __float2half(wv - __half2float(hi));
        sWhi[g * 72 + k] = hi;
        sWlo[g * 72 + k] = lo;
    }
    for (int i = tid; i < 2 * 2 * 16 * 72; i += 256) sH[i] = __float2half(0.f);
    __syncthreads();

    const int l  = tid & 31;
    const int w  = tid >> 5;
    const int mw = w & 3;
    const int nt = w >> 2;
    const int r  = l >> 2;
    const int cq = (l & 3) * 2;

    uint32_t Ahi[3][4][4], Alo[3][4][4];
    #pragma unroll
    for (int mt = 0; mt < 3; mt++) {
        const int g0 = 16 * mw + 64 * mt;
        #pragma unroll
        for (int kt = 0; kt < 4; kt++) {
            const int k0 = kt * 16 + cq;
            Ahi[mt][kt][0] = *(const uint32_t*)&sWhi[(g0 + r) * 72 + k0];
            Ahi[mt][kt][1] = *(const uint32_t*)&sWhi[(g0 + r + 8) * 72 + k0];
            Ahi[mt][kt][2] = *(const uint32_t*)&sWhi[(g0 + r) * 72 + k0 + 8];
            Ahi[mt][kt][3] = *(const uint32_t*)&sWhi[(g0 + r + 8) * 72 + k0 + 8];
            Alo[mt][kt][0] = *(const uint32_t*)&sWlo[(g0 + r) * 72 + k0];
            Alo[mt][kt][1] = *(const uint32_t*)&sWlo[(g0 + r + 8) * 72 + k0];
            Alo[mt][kt][2] = *(const uint32_t*)&sWlo[(g0 + r) * 72 + k0 + 8];
            Alo[mt][kt][3] = *(const uint32_t*)&sWlo[(g0 + r + 8) * 72 + k0 + 8];
        }
    }

    const int j0 = 16 * mw + r;
    const int j1 = j0 + 8;
    const int n0 = 8 * nt + cq;
    const float bhr0 = __ldg(b_hh + j0),        bhr1 = __ldg(b_hh + j1);
    const float bhz0 = __ldg(b_hh + 64 + j0),   bhz1 = __ldg(b_hh + 64 + j1);
    const float bhn0 = __ldg(b_hh + 128 + j0),  bhn1 = __ldg(b_hh + 128 + j1);
    const int seq0 = __ldg(seqlen + row0 + n0);
    const int seq1 = __ldg(seqlen + row0 + n0 + 1);

    float hp[4] = {0.f, 0.f, 0.f, 0.f};

    // xp plane base for this thread's bpair
    const size_t bp = (size_t)((row0 + n0) >> 1);
    const __half2* __restrict__ xplane = g_xp2 + bp * 192;
#define XPLANE(T) (xplane + (size_t)(T) * 1024 * 192)

    // two-deep prefetch: cur = t, nxt = t+1
    __half2 cur0 = XPLANE(0)[j0],       cur1 = XPLANE(0)[j1];
    __half2 cur2 = XPLANE(0)[64 + j0],  cur3 = XPLANE(0)[64 + j1];
    __half2 cur4 = XPLANE(0)[128 + j0], cur5 = XPLANE(0)[128 + j1];
    __half2 nxt0 = XPLANE(1)[j0],       nxt1 = XPLANE(1)[j1];
    __half2 nxt2 = XPLANE(1)[64 + j0],  nxt3 = XPLANE(1)[64 + j1];
    __half2 nxt4 = XPLANE(1)[128 + j0], nxt5 = XPLANE(1)[128 + j1];
    __syncthreads();

    for (int t = 0; t < TT; t++) {
        const int buf = t & 1;
        __half2 tm0, tm1, tm2, tm3, tm4, tm5;
        if (t + 2 < TT) {
            const __half2* pl = XPLANE(t + 2);
            tm0 = pl[j0];       tm1 = pl[j1];
            tm2 = pl[64 + j0];  tm3 = pl[64 + j1];
            tm4 = pl[128 + j0]; tm5 = pl[128 + j1];
        }

        uint32_t bhi[4][2], blo[4][2];
        const int bn = 8 * nt + r;
        #pragma unroll
        for (int kt = 0; kt < 4; kt++) {
            const int k0 = kt * 16 + cq;
            bhi[kt][0] = *(const uint32_t*)&SH(buf, 0, bn, k0);
            bhi[kt][1] = *(const uint32_t*)&SH(buf, 0, bn, k0 + 8);
            blo[kt][0] = *(const uint32_t*)&SH(buf, 1, bn, k0);
            blo[kt][1] = *(const uint32_t*)&SH(buf, 1, bn, k0 + 8);
        }

        float2 fR0 = __half22float2(cur0), fR1 = __half22float2(cur1);
        float2 fZ0 = __half22float2(cur2), fZ1 = __half22float2(cur3);
        float2 fN0 = __half22float2(cur4), fN1 = __half22float2(cur5);
        float acc[3][4];
        acc[0][0] = fR0.x + bhr0; acc[0][1] = fR0.y + bhr0;
        acc[0][2] = fR1.x + bhr1; acc[0][3] = fR1.y + bhr1;
        acc[1][0] = fZ0.x + bhz0; acc[1][1] = fZ0.y + bhz0;
        acc[1][2] = fZ1.x + bhz1; acc[1][3] = fZ1.y + bhz1;
        acc[2][0] = bhn0; acc[2][1] = bhn0;
        acc[2][2] = bhn1; acc[2][3] = bhn1;
        float fxn[4] = {fN0.x, fN0.y, fN1.x, fN1.y};

        #pragma unroll
        for (int mt = 0; mt < 3; mt++) {
            #pragma unroll
            for (int kt = 0; kt < 4; kt++) {
                asm volatile(
                    "mma.sync.aligned.m16n8k16.row.col.f32.f16.f16.f32 "
                    "{%0,%1,%2,%3}, {%4,%5,%6,%7}, {%8,%9}, {%0,%1,%2,%3};\n"
                    : "+f"(acc[mt][0]), "+f"(acc[mt][1]), "+f"(acc[mt][2]), "+f"(acc[mt][3])
                    : "r"(Ahi[mt][kt][0]), "r"(Ahi[mt][kt][1]), "r"(Ahi[mt][kt][2]), "r"(Ahi[mt][kt][3]),
                      "r"(bhi[kt][0]), "r"(bhi[kt][1]));
                asm volatile(
                    "mma.sync.aligned.m16n8k16.row.col.f32.f16.f16.f32 "
                    "{%0,%1,%2,%3}, {%4,%5,%6,%7}, {%8,%9}, {%0,%1,%2,%3};\n"
                    : "+f"(acc[mt][0]), "+f"(acc[mt][1]), "+f"(acc[mt][2]), "+f"(acc[mt][3])
                    : "r"(Ahi[mt][kt][0]), "r"(Ahi[mt][kt][1]), "r"(Ahi[mt][kt][2]), "r"(Ahi[mt][kt][3]),
                      "r"(blo[kt][0]), "r"(blo[kt][1]));
                asm volatile(
                    "mma.sync.aligned.m16n8k16.row.col.f32.f16.f16.f32 "
                    "{%0,%1,%2,%3}, {%4,%5,%6,%7}, {%8,%9}, {%0,%1,%2,%3};\n"
                    : "+f"(acc[mt][0]), "+f"(acc[mt][1]), "+f"(acc[mt][2]), "+f"(acc[mt][3])
                    : "r"(Alo[mt][kt][0]), "r"(Alo[mt][kt][1]), "r"(Alo[mt][kt][2]), "r"(Alo[mt][kt][3]),
                      "r"(bhi[kt][0]), "r"(bhi[kt][1]));
            }
        }

        #pragma unroll
        for (int e = 0; e < 4; e++) {
            float rr = sig_hw(acc[0][e]);
            float zz = sig_hw(acc[1][e]);
            float nn = tanh_hw(fxn[e] + rr * acc[2][e]);
            float hn = (1.f - zz) * nn + zz * hp[e];
            int sq = (e & 1) ? seq1 : seq0;
            hp[e] = (t < sq) ? hn : hp[e];
        }

        const int b2 = buf ^ 1;
        #pragma unroll
        for (int e = 0; e < 4; e++) {
            const int nn_ = n0 + (e & 1);
            const int jj_ = (e < 2) ? j0 : j1;
            __half hi = __float2half(hp[e]);
            __half lo = __float2half(hp[e] - __half2float(hi));
            SH(b2, 0, nn_, jj_) = hi;
            SH(b2, 1, nn_, jj_) = lo;
        }

        cur0 = nxt0; cur1 = nxt1; cur2 = nxt2; cur3 = nxt3; cur4 = nxt4; cur5 = nxt5;
        nxt0 = tm0; nxt1 = tm1; nxt2 = tm2; nxt3 = tm3; nxt4 = tm4; nxt5 = tm5;
        __syncthreads();
    }

    g_h[(size_t)(row0 + n0)     * HH + j0] = hp[0];
    g_h[(size_t)(row0 + n0 + 1) * HH + j0] = hp[1];
    g_h[(size_t)(row0 + n0)     * HH + j1] = hp[2];
    g_h[(size_t)(row0 + n0 + 1) * HH + j1] = hp[3];
#undef SH
#undef XPLANE
}

// =====================================================================
// Fused tail: z0 -> RK4 ODE -> decoder -> KL partials. (unchanged R7)
// =====================================================================
#define NSTEP 8
#define R4 4

__global__ void __launch_bounds__(128) tail_kernel(
    const float* __restrict__ eps,
    const float* __restrict__ Wz0, const float* __restrict__ bz0,
    const float* __restrict__ W1, const float* __restrict__ b1,
    const float* __restrict__ W2, const float* __restrict__ b2,
    const float* __restrict__ W3, const float* __restrict__ b3,
    const float* __restrict__ dW1, const float* __restrict__ db1,
    const float* __restrict__ dW2, const float* __restrict__ db2,
    float* __restrict__ out)
{
    __shared__ float sW1[32 * 64];
    __shared__ float sW2[64 * 64];
    __shared__ float sW3[64 * 32];
    __shared__ float sb1[64], sb2[64], sb3[32];
    __shared__ float sH[R4 * 64];
    __shared__ float z0p[R4 * 64];
    __shared__ float zc[32 * R4], za[32 * R4], zin[32 * R4], kb[32 * R4];
    __shared__ float sh1[64 * R4], sh2[64 * R4];

    const int tid = threadIdx.x;
    const int row0 = blockIdx.x * R4;

    for (int i = tid; i < OHH * LL; i += 128) {
        int o = i >> 5, f = i & 31;
        sW1[f * 64 + o] = W1[i];
    }
    for (int i = tid; i < LL * OHH; i += 128) {
        int l = i >> 6, f2 = i & 63;
        sW3[f2 * 32 + l] = W3[i];
    }
    for (int i = tid; i < OHH * OHH; i += 128) {
        int o = i >> 6, f = i & 63;
        sW2[f * 64 + o] = W2[i];
    }
    if (tid < 64) { sb1[tid] = b1[tid]; sb2[tid] = b2[tid]; }
    if (tid < 32) sb3[tid] = b3[tid];
    for (int i = tid; i < R4 * 64; i += 128)
        sH[i] = g_h[(size_t)(row0 + (i >> 6)) * HH + (i & 63)];
    __syncthreads();

    {
        const int o = tid & 63, rp = tid >> 6;
        float m0 = __ldg(bz0 + o), m1 = m0;
        #pragma unroll 8
        for (int f = 0; f < HH; f++) {
            float wv = __ldg(Wz0 + o * HH + f);
            m0 = fmaf(wv, sH[rp * 64 + f], m0);
            m1 = fmaf(wv, sH[(rp + 2) * 64 + f], m1);
        }
        z0p[rp * 64 + o] = m0;
        z0p[(rp + 2) * 64 + o] = m1;
    }
    __syncthreads();

    {
        const int row = tid >> 5, l = tid & 31;
        float m  = z0p[row * 64 + l];
        float lv = z0p[row * 64 + 32 + l];
        float z = m + eps[(size_t)(row0 + row) * LL + l] * __expf(0.5f * lv);
        zc[l * R4 + row] = z;
        float kt = 1.f + lv - m * m - __expf(lv);
        #pragma unroll
        for (int off = 16; off; off >>= 1) kt += __shfl_down_sync(0xffffffffu, kt, off);
        if (l == 0) g_klrow[row0 + row] = kt;
    }
    __syncthreads();

    const float hs = 48.0f / NSTEP;
    const int o64 = tid & 63, rp = tid >> 6;
    const int o32 = tid & 31, rw = tid >> 5;

#define ODE_EVAL(SRC)                                                        \
    {                                                                        \
        float a0 = sb1[o64], a1 = a0;                                        \
        _Pragma("unroll 8")                                                  \
        for (int f = 0; f < LL; f++) {                                       \
            float wv = sW1[f * 64 + o64];                                    \
            float4 zv = *(const float4*)((SRC) + f * R4);                    \
            float u0 = rp ? zv.y : zv.x;                                     \
            float u1 = rp ? zv.w : zv.z;                                     \
            a0 = fmaf(wv, u0, a0); a1 = fmaf(wv, u1, a1);                    \
        }                                                                    \
        sh1[o64 * R4 + rp]     = tanh_hw(a0);                                \
        sh1[o64 * R4 + rp + 2] = tanh_hw(a1);                                \
    }                                                                        \
    __syncthreads();                                                         \
    {                                                                        \
        float a0 = sb2[o64], a1 = a0;                                        \
        _Pragma("unroll 8")                                                  \
        for (int f = 0; f < OHH; f++) {                                      \
            float wv = sW2[f * 64 + o64];                                    \
            float4 zv = *(const float4*)(sh1 + f * R4);                      \
            float u0 = rp ? zv.y : zv.x;                                     \
            float u1 = rp ? zv.w : zv.z;                                     \
            a0 = fmaf(wv, u0, a0); a1 = fmaf(wv, u1, a1);                    \
        }                                                                    \
        sh2[o64 * R4 + rp]     = tanh_hw(a0);                                \
        sh2[o64 * R4 + rp + 2] = tanh_hw(a1);                                \
    }                                                                        \
    __syncthreads();                                                         \
    {                                                                        \
        float a = sb3[o32];                                                  \
        _Pragma("unroll 8")                                                  \
        for (int f = 0; f < OHH; f++)                                        \
            a = fmaf(sW3[f * 32 + o32], sh2[f * R4 + rw], a);                \
        kb[o32 * R4 + rw] = a;                                               \
    }                                                                        \
    __syncthreads();

    for (int s = 0; s < NSTEP; s++) {
        ODE_EVAL(zc)
        za[tid]  = fmaf(hs / 6.f, kb[tid], zc[tid]);
        zin[tid] = fmaf(hs * 0.5f, kb[tid], zc[tid]);
        __syncthreads();
        ODE_EVAL(zin)
        za[tid]  = fmaf(hs / 3.f, kb[tid], za[tid]);
        zin[tid] = fmaf(hs * 0.5f, kb[tid], zc[tid]);
        __syncthreads();
        ODE_EVAL(zin)
        za[tid]  = fmaf(hs / 3.f, kb[tid], za[tid]);
        zin[tid] = fmaf(hs, kb[tid], zc[tid]);
        __syncthreads();
        ODE_EVAL(zin)
        zc[tid] = fmaf(hs / 6.f, kb[tid], za[tid]);
        __syncthreads();
    }
#undef ODE_EVAL

    {
        float a0 = __ldg(db1 + o64), a1 = a0;
        #pragma unroll 8
        for (int f = 0; f < LL; f++) {
            float wv = __ldg(dW1 + o64 * LL + f);
            float4 zv = *(const float4*)(zc + f * R4);
            float u0 = rp ? zv.y : zv.x;
            float u1 = rp ? zv.w : zv.z;
            a0 = fmaf(wv, u0, a0); a1 = fmaf(wv, u1, a1);
        }
        float w2 = __ldg(dW2 + o64);
        sh1[o64 * R4 + rp]     = fmaxf(a0, 0.f) * w2;
        sh1[o64 * R4 + rp + 2] = fmaxf(a1, 0.f) * w2;
    }
    __syncthreads();
    {
        const int row = tid >> 5, l = tid & 31;
        float s = sh1[l * R4 + row] + sh1[(l + 32) * R4 + row];
        #pragma unroll
        for (int off = 16; off; off >>= 1) s += __shfl_down_sync(0xffffffffu, s, off);
        if (l == 0) out[row0 + row] = s + __ldg(db2);
    }
}

__global__ void __launch_bounds__(1024) kl_kernel(float* __restrict__ out)
{
    __shared__ float s[1024];
    const int t = threadIdx.x;
    s[t] = g_klrow[t] + g_klrow[t + 1024];
    __syncthreads();
    for (int o = 512; o; o >>= 1) {
        if (t < o) s[t] += s[t + o];
        __syncthreads();
    }
    if (t == 0) out[BB] = -0.5f * s[0] / ((float)BB * (float)LL);
}

// =====================================================================
extern "C" void kernel_launch(void* const* d_in, const int* in_sizes, int n_in,
                              void* d_out, int out_size)
{
    const float* values = (const float*)d_in[1];
    const float* maskp  = (const float*)d_in[2];
    const int*   seql   = (const int*)d_in[3];
    const float* eps    = (const float*)d_in[4];
    const float* W_ih   = (const float*)d_in[5];
    const float* W_hh   = (const float*)d_in[6];
    const float* b_ih   = (const float*)d_in[7];
    const float* b_hh   = (const float*)d_in[8];
    const float* W_z0   = (const float*)d_in[9];
    const float* b_z0   = (const float*)d_in[10];
    const float* oW1    = (const float*)d_in[11];
    const float* ob1    = (const float*)d_in[12];
    const float* oW2    = (const float*)d_in[13];
    const float* ob2    = (const float*)d_in[14];
    const float* oW3    = (const float*)d_in[15];
    const float* ob3    = (const float*)d_in[16];
    const float* dW1    = (const float*)d_in[17];
    const float* db1    = (const float*)d_in[18];
    const float* dW2    = (const float*)d_in[19];
    const float* db2    = (const float*)d_in[20];
    float* out = (float*)d_out;

    cudaFuncSetAttribute(gru_kernel, cudaFuncAttributeMaxDynamicSharedMemorySize, GRU_SMEM_B);

    xp_kernel<<<dim3(16, 64), 256>>>(values, maskp, W_ih, b_ih);
    gru_kernel<<<128, 256, GRU_SMEM_B>>>(seql, W_hh, b_hh);
    tail_kernel<<<512, 128>>>(eps, W_z0, b_z0, oW1, ob1, oW2, ob2, oW3, ob3,
                              dW1, db1, dW2, db2, out);
    kl_kernel<<<1, 1024>>>(out);
}

// round 10
// speedup vs baseline: 3.1766x; 1.1002x over previous
#include <cuda_runtime.h>
#include <cuda_fp16.h>
#include <cstdint>

#define BB 2048
#define TT 256
#define NVV 32
#define HH 64
#define GG 192
#define LL 32
#define OHH 64

__device__ float g_h[BB * HH];
__device__ float g_klrow[BB];
// xp planes: [t][bpair(1024)][g(192)] as half2 (pair = 2 batch rows). 201 MB.
__device__ __half2 g_xp2[(size_t)TT * 1024 * GG];

__device__ __forceinline__ float tanh_hw(float x) {
    float y;
    asm("tanh.approx.f32 %0, %1;" : "=f"(y) : "f"(x));
    return y;
}
__device__ __forceinline__ float sig_hw(float x) {
    return fmaf(tanh_hw(0.5f * x), 0.5f, 0.5f);
}

// =====================================================================
// xp GEMM via fp16 tensor cores, fp32 accumulate.
// grid (16 b-blocks, 64 t-blocks) x 256 thr; 4 t per CTA (W staged once).
// Output layout: g_xp2[((t*1024)+bpair)*192 + g]
// =====================================================================
__global__ void __launch_bounds__(256) xp_kernel(
    const float* __restrict__ values, const float* __restrict__ maskp,
    const float* __restrict__ W_ih, const float* __restrict__ b_ih)
{
    __shared__ __half sW[192 * 72];
    __shared__ __half sX[128 * 72];

    const int tid = threadIdx.x;
    const int bbase = blockIdx.x * 128;

    for (int i = tid; i < GG * HH; i += 256) {
        int g = i >> 6, f = i & 63;
        sW[g * 72 + f] = __float2half(W_ih[i]);
    }

    const int w = tid >> 5, l = tid & 31;
    const int wg = w >> 2;
    const int wb = w & 3;
    const int l4 = l >> 2;
    const int l2 = (l & 3) * 2;

    for (int tloc = 0; tloc < 4; tloc++) {
        const int t = blockIdx.y * 4 + tloc;
        const int tt = TT - 1 - t;

        if (tloc > 0) __syncthreads();
        for (int i = tid; i < 128 * HH; i += 256) {
            int bl = i >> 6, f = i & 63;
            size_t base = (size_t)(bbase + bl) * TT * NVV + (size_t)tt * NVV;
            float v = (f < NVV) ? values[base + f] : maskp[base + f - NVV];
            sX[bl * 72 + f] = __float2half(v);
        }
        __syncthreads();

        #pragma unroll
        for (int gt = 0; gt < 6; gt++) {
            const int g0 = wg * 96 + gt * 16;
            uint32_t a[4][4];
            #pragma unroll
            for (int kk = 0; kk < 4; kk++) {
                const __half* p = &sW[(g0 + l4) * 72 + kk * 16 + l2];
                a[kk][0] = *(const uint32_t*)(p);
                a[kk][1] = *(const uint32_t*)(p + 8 * 72);
                a[kk][2] = *(const uint32_t*)(p + 8);
                a[kk][3] = *(const uint32_t*)(p + 8 * 72 + 8);
            }
            const float bias0 = __ldg(b_ih + g0 + l4);
            const float bias1 = __ldg(b_ih + g0 + 8 + l4);

            #pragma unroll
            for (int bt = 0; bt < 4; bt++) {
                const int b0 = wb * 32 + bt * 8;
                float c0 = bias0, c1 = bias0, c2 = bias1, c3 = bias1;
                #pragma unroll
                for (int kk = 0; kk < 4; kk++) {
                    const __half* bp = &sX[(b0 + l4) * 72 + kk * 16 + l2];
                    uint32_t br0 = *(const uint32_t*)(bp);
                    uint32_t br1 = *(const uint32_t*)(bp + 8);
                    asm volatile(
                        "mma.sync.aligned.m16n8k16.row.col.f32.f16.f16.f32 "
                        "{%0,%1,%2,%3}, {%4,%5,%6,%7}, {%8,%9}, {%0,%1,%2,%3};\n"
                        : "+f"(c0), "+f"(c1), "+f"(c2), "+f"(c3)
                        : "r"(a[kk][0]), "r"(a[kk][1]), "r"(a[kk][2]), "r"(a[kk][3]),
                          "r"(br0), "r"(br1));
                }
                const int gg = g0 + l4;
                const int bpair = (bbase + b0 + l2) >> 1;
                size_t base = ((size_t)t * 1024 + bpair) * 192 + gg;
                g_xp2[base]     = __floats2half2_rn(c0, c1);
                g_xp2[base + 8] = __floats2half2_rn(c2, c3);
            }
        }
    }
}

// =====================================================================
// GRU scan: split-fp16 tensor-core h-matvec, 2-term (W exact, h fp16):
//   D = Whi@h16 + Wlo@h16   (fp32 accumulate)
// h state kept fp32 in registers; only the matvec input is rounded.
// 24 HMMA/warp/step, single h plane in SMEM, 1 sync/step.
// =====================================================================
#define GRU_SMEM_B ((192*72*2 + 2*16*72) * 2)

__global__ void __launch_bounds__(256, 1) gru_kernel(
    const int* __restrict__ seqlen,
    const float* __restrict__ W_hh, const float* __restrict__ b_hh)
{
    extern __shared__ char smem[];
    __half* sWhi = (__half*)smem;            // [192][72]
    __half* sWlo = sWhi + 192 * 72;          // [192][72]
    __half* sH   = sWlo + 192 * 72;          // [2][16][72]
#define SH(buf, n, k) sH[(((buf) * 16) + (n)) * 72 + (k)]

    const int tid  = threadIdx.x;
    const int row0 = blockIdx.x * 16;

    for (int i = tid; i < GG * HH; i += 256) {
        int g = i >> 6, k = i & 63;
        float wv = W_hh[i];
        __half hi = __float2half(wv);
        __half lo = __float2half(wv - __half2float(hi));
        sWhi[g * 72 + k] = hi;
        sWlo[g * 72 + k] = lo;
    }
    for (int i = tid; i < 2 * 16 * 72; i += 256) sH[i] = __float2half(0.f);
    __syncthreads();

    const int l  = tid & 31;
    const int w  = tid >> 5;
    const int mw = w & 3;
    const int nt = w >> 2;
    const int r  = l >> 2;
    const int cq = (l & 3) * 2;

    uint32_t Ahi[3][4][4], Alo[3][4][4];
    #pragma unroll
    for (int mt = 0; mt < 3; mt++) {
        const int g0 = 16 * mw + 64 * mt;
        #pragma unroll
        for (int kt = 0; kt < 4; kt++) {
            const int k0 = kt * 16 + cq;
            Ahi[mt][kt][0] = *(const uint32_t*)&sWhi[(g0 + r) * 72 + k0];
            Ahi[mt][kt][1] = *(const uint32_t*)&sWhi[(g0 + r + 8) * 72 + k0];
            Ahi[mt][kt][2] = *(const uint32_t*)&sWhi[(g0 + r) * 72 + k0 + 8];
            Ahi[mt][kt][3] = *(const uint32_t*)&sWhi[(g0 + r + 8) * 72 + k0 + 8];
            Alo[mt][kt][0] = *(const uint32_t*)&sWlo[(g0 + r) * 72 + k0];
            Alo[mt][kt][1] = *(const uint32_t*)&sWlo[(g0 + r + 8) * 72 + k0];
            Alo[mt][kt][2] = *(const uint32_t*)&sWlo[(g0 + r) * 72 + k0 + 8];
            Alo[mt][kt][3] = *(const uint32_t*)&sWlo[(g0 + r + 8) * 72 + k0 + 8];
        }
    }

    const int j0 = 16 * mw + r;
    const int j1 = j0 + 8;
    const int n0 = 8 * nt + cq;
    const float bhr0 = __ldg(b_hh + j0),        bhr1 = __ldg(b_hh + j1);
    const float bhz0 = __ldg(b_hh + 64 + j0),   bhz1 = __ldg(b_hh + 64 + j1);
    const float bhn0 = __ldg(b_hh + 128 + j0),  bhn1 = __ldg(b_hh + 128 + j1);
    const int seq0 = __ldg(seqlen + row0 + n0);
    const int seq1 = __ldg(seqlen + row0 + n0 + 1);

    float hp[4] = {0.f, 0.f, 0.f, 0.f};

    const size_t bp = (size_t)((row0 + n0) >> 1);
    const __half2* __restrict__ xplane = g_xp2 + bp * 192;
#define XPLANE(T) (xplane + (size_t)(T) * 1024 * 192)

    __half2 cur0 = XPLANE(0)[j0],       cur1 = XPLANE(0)[j1];
    __half2 cur2 = XPLANE(0)[64 + j0],  cur3 = XPLANE(0)[64 + j1];
    __half2 cur4 = XPLANE(0)[128 + j0], cur5 = XPLANE(0)[128 + j1];
    __half2 nxt0 = XPLANE(1)[j0],       nxt1 = XPLANE(1)[j1];
    __half2 nxt2 = XPLANE(1)[64 + j0],  nxt3 = XPLANE(1)[64 + j1];
    __half2 nxt4 = XPLANE(1)[128 + j0], nxt5 = XPLANE(1)[128 + j1];
    __syncthreads();

    for (int t = 0; t < TT; t++) {
        const int buf = t & 1;
        __half2 tm0, tm1, tm2, tm3, tm4, tm5;
        if (t + 2 < TT) {
            const __half2* pl = XPLANE(t + 2);
            tm0 = pl[j0];       tm1 = pl[j1];
            tm2 = pl[64 + j0];  tm3 = pl[64 + j1];
            tm4 = pl[128 + j0]; tm5 = pl[128 + j1];
        }

        uint32_t bhi[4][2];
        const int bn = 8 * nt + r;
        #pragma unroll
        for (int kt = 0; kt < 4; kt++) {
            const int k0 = kt * 16 + cq;
            bhi[kt][0] = *(const uint32_t*)&SH(buf, bn, k0);
            bhi[kt][1] = *(const uint32_t*)&SH(buf, bn, k0 + 8);
        }

        float2 fR0 = __half22float2(cur0), fR1 = __half22float2(cur1);
        float2 fZ0 = __half22float2(cur2), fZ1 = __half22float2(cur3);
        float2 fN0 = __half22float2(cur4), fN1 = __half22float2(cur5);
        float acc[3][4];
        acc[0][0] = fR0.x + bhr0; acc[0][1] = fR0.y + bhr0;
        acc[0][2] = fR1.x + bhr1; acc[0][3] = fR1.y + bhr1;
        acc[1][0] = fZ0.x + bhz0; acc[1][1] = fZ0.y + bhz0;
        acc[1][2] = fZ1.x + bhz1; acc[1][3] = fZ1.y + bhz1;
        acc[2][0] = bhn0; acc[2][1] = bhn0;
        acc[2][2] = bhn1; acc[2][3] = bhn1;
        float fxn[4] = {fN0.x, fN0.y, fN1.x, fN1.y};

        #pragma unroll
        for (int mt = 0; mt < 3; mt++) {
            #pragma unroll
            for (int kt = 0; kt < 4; kt++) {
                asm volatile(
                    "mma.sync.aligned.m16n8k16.row.col.f32.f16.f16.f32 "
                    "{%0,%1,%2,%3}, {%4,%5,%6,%7}, {%8,%9}, {%0,%1,%2,%3};\n"
                    : "+f"(acc[mt][0]), "+f"(acc[mt][1]), "+f"(acc[mt][2]), "+f"(acc[mt][3])
                    : "r"(Ahi[mt][kt][0]), "r"(Ahi[mt][kt][1]), "r"(Ahi[mt][kt][2]), "r"(Ahi[mt][kt][3]),
                      "r"(bhi[kt][0]), "r"(bhi[kt][1]));
                asm volatile(
                    "mma.sync.aligned.m16n8k16.row.col.f32.f16.f16.f32 "
                    "{%0,%1,%2,%3}, {%4,%5,%6,%7}, {%8,%9}, {%0,%1,%2,%3};\n"
                    : "+f"(acc[mt][0]), "+f"(acc[mt][1]), "+f"(acc[mt][2]), "+f"(acc[mt][3])
                    : "r"(Alo[mt][kt][0]), "r"(Alo[mt][kt][1]), "r"(Alo[mt][kt][2]), "r"(Alo[mt][kt][3]),
                      "r"(bhi[kt][0]), "r"(bhi[kt][1]));
            }
        }

        #pragma unroll
        for (int e = 0; e < 4; e++) {
            float rr = sig_hw(acc[0][e]);
            float zz = sig_hw(acc[1][e]);
            float nn = tanh_hw(fxn[e] + rr * acc[2][e]);
            float hn = (1.f - zz) * nn + zz * hp[e];
            int sq = (e & 1) ? seq1 : seq0;
            hp[e] = (t < sq) ? hn : hp[e];
        }

        const int b2 = buf ^ 1;
        #pragma unroll
        for (int e = 0; e < 4; e++) {
            const int nn_ = n0 + (e & 1);
            const int jj_ = (e < 2) ? j0 : j1;
            SH(b2, nn_, jj_) = __float2half(hp[e]);
        }

        cur0 = nxt0; cur1 = nxt1; cur2 = nxt2; cur3 = nxt3; cur4 = nxt4; cur5 = nxt5;
        nxt0 = tm0; nxt1 = tm1; nxt2 = tm2; nxt3 = tm3; nxt4 = tm4; nxt5 = tm5;
        __syncthreads();
    }

    g_h[(size_t)(row0 + n0)     * HH + j0] = hp[0];
    g_h[(size_t)(row0 + n0 + 1) * HH + j0] = hp[1];
    g_h[(size_t)(row0 + n0)     * HH + j1] = hp[2];
    g_h[(size_t)(row0 + n0 + 1) * HH + j1] = hp[3];
#undef SH
#undef XPLANE
}

// =====================================================================
// Fused tail: z0 -> RK4 ODE -> decoder -> KL partials. (unchanged)
// =====================================================================
#define NSTEP 8
#define R4 4

__global__ void __launch_bounds__(128) tail_kernel(
    const float* __restrict__ eps,
    const float* __restrict__ Wz0, const float* __restrict__ bz0,
    const float* __restrict__ W1, const float* __restrict__ b1,
    const float* __restrict__ W2, const float* __restrict__ b2,
    const float* __restrict__ W3, const float* __restrict__ b3,
    const float* __restrict__ dW1, const float* __restrict__ db1,
    const float* __restrict__ dW2, const float* __restrict__ db2,
    float* __restrict__ out)
{
    __shared__ float sW1[32 * 64];
    __shared__ float sW2[64 * 64];
    __shared__ float sW3[64 * 32];
    __shared__ float sb1[64], sb2[64], sb3[32];
    __shared__ float sH[R4 * 64];
    __shared__ float z0p[R4 * 64];
    __shared__ float zc[32 * R4], za[32 * R4], zin[32 * R4], kb[32 * R4];
    __shared__ float sh1[64 * R4], sh2[64 * R4];

    const int tid = threadIdx.x;
    const int row0 = blockIdx.x * R4;

    for (int i = tid; i < OHH * LL; i += 128) {
        int o = i >> 5, f = i & 31;
        sW1[f * 64 + o] = W1[i];
    }
    for (int i = tid; i < LL * OHH; i += 128) {
        int l = i >> 6, f2 = i & 63;
        sW3[f2 * 32 + l] = W3[i];
    }
    for (int i = tid; i < OHH * OHH; i += 128) {
        int o = i >> 6, f = i & 63;
        sW2[f * 64 + o] = W2[i];
    }
    if (tid < 64) { sb1[tid] = b1[tid]; sb2[tid] = b2[tid]; }
    if (tid < 32) sb3[tid] = b3[tid];
    for (int i = tid; i < R4 * 64; i += 128)
        sH[i] = g_h[(size_t)(row0 + (i >> 6)) * HH + (i & 63)];
    __syncthreads();

    {
        const int o = tid & 63, rp = tid >> 6;
        float m0 = __ldg(bz0 + o), m1 = m0;
        #pragma unroll 8
        for (int f = 0; f < HH; f++) {
            float wv = __ldg(Wz0 + o * HH + f);
            m0 = fmaf(wv, sH[rp * 64 + f], m0);
            m1 = fmaf(wv, sH[(rp + 2) * 64 + f], m1);
        }
        z0p[rp * 64 + o] = m0;
        z0p[(rp + 2) * 64 + o] = m1;
    }
    __syncthreads();

    {
        const int row = tid >> 5, l = tid & 31;
        float m  = z0p[row * 64 + l];
        float lv = z0p[row * 64 + 32 + l];
        float z = m + eps[(size_t)(row0 + row) * LL + l] * __expf(0.5f * lv);
        zc[l * R4 + row] = z;
        float kt = 1.f + lv - m * m - __expf(lv);
        #pragma unroll
        for (int off = 16; off; off >>= 1) kt += __shfl_down_sync(0xffffffffu, kt, off);
        if (l == 0) g_klrow[row0 + row] = kt;
    }
    __syncthreads();

    const float hs = 48.0f / NSTEP;
    const int o64 = tid & 63, rp = tid >> 6;
    const int o32 = tid & 31, rw = tid >> 5;

#define ODE_EVAL(SRC)                                                        \
    {                                                                        \
        float a0 = sb1[o64], a1 = a0;                                        \
        _Pragma("unroll 8")                                                  \
        for (int f = 0; f < LL; f++) {                                       \
            float wv = sW1[f * 64 + o64];                                    \
            float4 zv = *(const float4*)((SRC) + f * R4);                    \
            float u0 = rp ? zv.y : zv.x;                                     \
            float u1 = rp ? zv.w : zv.z;                                     \
            a0 = fmaf(wv, u0, a0); a1 = fmaf(wv, u1, a1);                    \
        }                                                                    \
        sh1[o64 * R4 + rp]     = tanh_hw(a0);                                \
        sh1[o64 * R4 + rp + 2] = tanh_hw(a1);                                \
    }                                                                        \
    __syncthreads();                                                         \
    {                                                                        \
        float a0 = sb2[o64], a1 = a0;                                        \
        _Pragma("unroll 8")                                                  \
        for (int f = 0; f < OHH; f++) {                                      \
            float wv = sW2[f * 64 + o64];                                    \
            float4 zv = *(const float4*)(sh1 + f * R4);                      \
            float u0 = rp ? zv.y : zv.x;                                     \
            float u1 = rp ? zv.w : zv.z;                                     \
            a0 = fmaf(wv, u0, a0); a1 = fmaf(wv, u1, a1);                    \
        }                                                                    \
        sh2[o64 * R4 + rp]     = tanh_hw(a0);                                \
        sh2[o64 * R4 + rp + 2] = tanh_hw(a1);                                \
    }                                                                        \
    __syncthreads();                                                         \
    {                                                                        \
        float a = sb3[o32];                                                  \
        _Pragma("unroll 8")                                                  \
        for (int f = 0; f < OHH; f++)                                        \
            a = fmaf(sW3[f * 32 + o32], sh2[f * R4 + rw], a);                \
        kb[o32 * R4 + rw] = a;                                               \
    }                                                                        \
    __syncthreads();

    for (int s = 0; s < NSTEP; s++) {
        ODE_EVAL(zc)
        za[tid]  = fmaf(hs / 6.f, kb[tid], zc[tid]);
        zin[tid] = fmaf(hs * 0.5f, kb[tid], zc[tid]);
        __syncthreads();
        ODE_EVAL(zin)
        za[tid]  = fmaf(hs / 3.f, kb[tid], za[tid]);
        zin[tid] = fmaf(hs * 0.5f, kb[tid], zc[tid]);
        __syncthreads();
        ODE_EVAL(zin)
        za[tid]  = fmaf(hs / 3.f, kb[tid], za[tid]);
        zin[tid] = fmaf(hs, kb[tid], zc[tid]);
        __syncthreads();
        ODE_EVAL(zin)
        zc[tid] = fmaf(hs / 6.f, kb[tid], za[tid]);
        __syncthreads();
    }
#undef ODE_EVAL

    {
        float a0 = __ldg(db1 + o64), a1 = a0;
        #pragma unroll 8
        for (int f = 0; f < LL; f++) {
            float wv = __ldg(dW1 + o64 * LL + f);
            float4 zv = *(const float4*)(zc + f * R4);
            float u0 = rp ? zv.y : zv.x;
            float u1 = rp ? zv.w : zv.z;
            a0 = fmaf(wv, u0, a0); a1 = fmaf(wv, u1, a1);
        }
        float w2 = __ldg(dW2 + o64);
        sh1[o64 * R4 + rp]     = fmaxf(a0, 0.f) * w2;
        sh1[o64 * R4 + rp + 2] = fmaxf(a1, 0.f) * w2;
    }
    __syncthreads();
    {
        const int row = tid >> 5, l = tid & 31;
        float s = sh1[l * R4 + row] + sh1[(l + 32) * R4 + row];
        #pragma unroll
        for (int off = 16; off; off >>= 1) s += __shfl_down_sync(0xffffffffu, s, off);
        if (l == 0) out[row0 + row] = s + __ldg(db2);
    }
}

__global__ void __launch_bounds__(1024) kl_kernel(float* __restrict__ out)
{
    __shared__ float s[1024];
    const int t = threadIdx.x;
    s[t] = g_klrow[t] + g_klrow[t + 1024];
    __syncthreads();
    for (int o = 512; o; o >>= 1) {
        if (t < o) s[t] += s[t + o];
        __syncthreads();
    }
    if (t == 0) out[BB] = -0.5f * s[0] / ((float)BB * (float)LL);
}

// =====================================================================
extern "C" void kernel_launch(void* const* d_in, const int* in_sizes, int n_in,
                              void* d_out, int out_size)
{
    const float* values = (const float*)d_in[1];
    const float* maskp  = (const float*)d_in[2];
    const int*   seql   = (const int*)d_in[3];
    const float* eps    = (const float*)d_in[4];
    const float* W_ih   = (const float*)d_in[5];
    const float* W_hh   = (const float*)d_in[6];
    const float* b_ih   = (const float*)d_in[7];
    const float* b_hh   = (const float*)d_in[8];
    const float* W_z0   = (const float*)d_in[9];
    const float* b_z0   = (const float*)d_in[10];
    const float* oW1    = (const float*)d_in[11];
    const float* ob1    = (const float*)d_in[12];
    const float* oW2    = (const float*)d_in[13];
    const float* ob2    = (const float*)d_in[14];
    const float* oW3    = (const float*)d_in[15];
    const float* ob3    = (const float*)d_in[16];
    const float* dW1    = (const float*)d_in[17];
    const float* db1    = (const float*)d_in[18];
    const float* dW2    = (const float*)d_in[19];
    const float* db2    = (const float*)d_in[20];
    float* out = (float*)d_out;

    cudaFuncSetAttribute(gru_kernel, cudaFuncAttributeMaxDynamicSharedMemorySize, GRU_SMEM_B);

    xp_kernel<<<dim3(16, 64), 256>>>(values, maskp, W_ih, b_ih);
    gru_kernel<<<128, 256, GRU_SMEM_B>>>(seql, W_hh, b_hh);
    tail_kernel<<<512, 128>>>(eps, W_z0, b_z0, oW1, ob1, oW2, ob2, oW3, ob3,
                              dW1, db1, dW2, db2, out);
    kl_kernel<<<1, 1024>>>(out);
}